// round 12
// baseline (speedup 1.0000x reference)
#include <cuda_runtime.h>
#include <cuda_fp16.h>
#include <math.h>
#include <stdint.h>

#define NN   50000
#define NE   800000
#define IND  256
#define D1   128   // HEADS*HIDDEN
#define D2   64    // OUT_DIM
#define CAP  128   // max in-degree capacity (Poisson(16) max ~50; 128 is safe)

// ------------------------- device scratch (no allocs) -------------------------
__device__ __half g_z1h[(size_t)NN * D1];      // layer-1 projections (fp16, gather-only)
__device__ uint16_t g_h1h[(size_t)NN * D1];    // elu(h1) bf16 hi plane
__device__ uint16_t g_h1l[(size_t)NN * D1];    // elu(h1) bf16 lo plane
__device__ __half g_z2h[(size_t)NN * D2];      // layer-2 projections (fp16, gather-only)
__device__ float g_es1[NN * 4], g_ed1[NN * 4];
__device__ float g_es2[NN],     g_ed2[NN];
__device__ int   g_cnt[NN];                    // in-degree (self-cleaning: agg2 re-zeros)
__device__ int   g_slots[(size_t)NN * CAP];    // src lists per dst (slot table)

__device__ __forceinline__ float lrelu(float x) { return x > 0.f ? x : 0.01f * x; }

// packed f32x2 helpers (Blackwell dual-FMA)
__device__ __forceinline__ unsigned long long pack2(float x, float y) {
    unsigned long long r;
    asm("mov.b64 %0, {%1, %2};" : "=l"(r) : "f"(x), "f"(y));
    return r;
}
__device__ __forceinline__ void unpack2(unsigned long long v, float& x, float& y) {
    asm("mov.b64 {%0, %1}, %2;" : "=f"(x), "=f"(y) : "l"(v));
}
__device__ __forceinline__ void ffma2(unsigned long long& acc,
                                      unsigned long long a, unsigned long long b) {
    asm("fma.rn.f32x2 %0, %1, %2, %0;" : "+l"(acc) : "l"(a), "l"(b));
}

// ------------------------- slot-table build -------------------------
__global__ void fill_k(const int* __restrict__ src, const int* __restrict__ dst) {
    int e = blockIdx.x * blockDim.x + threadIdx.x;
    if (e >= NE) return;
    int d = dst[e];
    int pos = atomicAdd(&g_cnt[d], 1);
    if (pos < CAP) g_slots[(size_t)d * CAP + pos] = src[e];
}

// ------------------------- bf16 3-term split GEMM (tensor core) -------------
__device__ __forceinline__ void bfsplit2(float x, float y, uint32_t& hi, uint32_t& lo) {
    asm("cvt.rn.bf16x2.f32 %0, %1, %2;" : "=r"(hi) : "f"(y), "f"(x));
    float hx = __uint_as_float(hi << 16);
    float hy = __uint_as_float(hi & 0xFFFF0000u);
    float lx = x - hx, ly = y - hy;
    asm("cvt.rn.bf16x2.f32 %0, %1, %2;" : "=r"(lo) : "f"(ly), "f"(lx));
}

__device__ __forceinline__ void ldmx2t(uint32_t& r0, uint32_t& r1, uint32_t addr) {
    asm volatile("ldmatrix.sync.aligned.m8n8.x2.trans.shared.b16 {%0,%1}, [%2];"
                 : "=r"(r0), "=r"(r1) : "r"(addr));
}

__device__ __forceinline__ void mma16816(float c[4], const uint32_t a[4],
                                         const uint32_t b[2]) {
    asm volatile(
        "mma.sync.aligned.m16n8k16.row.col.f32.bf16.bf16.f32 "
        "{%0,%1,%2,%3}, {%4,%5,%6,%7}, {%8,%9}, {%0,%1,%2,%3};"
        : "+f"(c[0]), "+f"(c[1]), "+f"(c[2]), "+f"(c[3])
        : "r"(a[0]), "r"(a[1]), "r"(a[2]), "r"(a[3]), "r"(b[0]), "r"(b[1]));
}

template <bool PERM>
__device__ __forceinline__ float4 ldB(const float* __restrict__ B, int N,
                                      int row, int col) {
    if (PERM) {
        int h = col >> 5, o = col & 31;
        return *(const float4*)(B + h * (IND * 32) + row * 32 + o);
    }
    return *(const float4*)(B + (size_t)row * N + col);
}

// C[M,N] = A[M,K] * B[K,N]; C stored fp16. ASPLIT: A given as bf16 hi/lo planes.
// EPI==1: fused 4-head es/ed epilogue. EPI==2: single-head es/ed (smem join).
template <int BM, int BN, int BK, int WARPS_M, int WARPS_N, bool PERM, int EPI, bool ASPLIT>
__global__ __launch_bounds__(WARPS_M * WARPS_N * 32, 1)
void mma_gemm(const float* __restrict__ A,
              const uint16_t* __restrict__ Ahg, const uint16_t* __restrict__ Alg,
              const float* __restrict__ B,
              __half* __restrict__ Ch, const float* __restrict__ av,
              int M, int N, int K) {
    constexpr int WM = 64, WN = 32;
    constexpr int MT = WM / 16, NT = WN / 8;
    constexpr int THREADS = WARPS_M * WARPS_N * 32;
    constexpr int LA = BM * BK / 4 / THREADS;
    constexpr int LB = BK * BN / 4 / THREADS;
    constexpr int AST = BK + 8;
    constexpr int BST = BN + 8;

    __shared__ alignas(16) uint16_t Ah[BM * AST], Al[BM * AST];
    __shared__ alignas(16) uint16_t Bh[BK * BST], Bl[BK * BST];
    __shared__ float s_red[(EPI == 2) ? 2 * BM * 2 : 1];

    int tid  = threadIdx.x;
    int warp = tid >> 5, lane = tid & 31;
    int g = lane >> 2, tig = lane & 3;
    int wm0 = (warp / WARPS_N) * WM;
    int wn0 = (warp % WARPS_N) * WN;
    int m0  = blockIdx.x * BM;

    uint32_t bh_u32 = (uint32_t)__cvta_generic_to_shared(Bh);
    uint32_t bl_u32 = (uint32_t)__cvta_generic_to_shared(Bl);

    float c[MT][NT][4];
#pragma unroll
    for (int i = 0; i < MT; i++)
#pragma unroll
        for (int j = 0; j < NT; j++)
#pragma unroll
            for (int v = 0; v < 4; v++) c[i][j][v] = 0.f;

    float4 pa[LA], pb[LB];
    uint2 pah[LA], pal[LA];
    int ar[LA], ac[LA], br[LB], bc[LB];
#pragma unroll
    for (int it = 0; it < LA; it++) {
        int i = it * THREADS + tid;
        ar[it] = i / (BK / 4);
        ac[it] = (i % (BK / 4)) * 4;
    }
#pragma unroll
    for (int it = 0; it < LB; it++) {
        int i = it * THREADS + tid;
        br[it] = i / (BN / 4);
        bc[it] = (i % (BN / 4)) * 4;
    }

    // preload tile 0
#pragma unroll
    for (int it = 0; it < LA; it++) {
        int gr = m0 + ar[it]; if (gr >= M) gr = M - 1;
        if (ASPLIT) {
            pah[it] = *(const uint2*)(Ahg + (size_t)gr * K + ac[it]);
            pal[it] = *(const uint2*)(Alg + (size_t)gr * K + ac[it]);
        } else {
            pa[it] = *(const float4*)(A + (size_t)gr * K + ac[it]);
        }
    }
#pragma unroll
    for (int it = 0; it < LB; it++)
        pb[it] = ldB<PERM>(B, N, br[it], bc[it]);
#pragma unroll
    for (int it = 0; it < LA; it++) {
        int base = ar[it] * AST + ac[it];
        if (ASPLIT) {
            *(uint32_t*)&Ah[base] = pah[it].x; *(uint32_t*)&Ah[base + 2] = pah[it].y;
            *(uint32_t*)&Al[base] = pal[it].x; *(uint32_t*)&Al[base + 2] = pal[it].y;
        } else {
            uint32_t h0, l0, h1, l1;
            bfsplit2(pa[it].x, pa[it].y, h0, l0);
            bfsplit2(pa[it].z, pa[it].w, h1, l1);
            *(uint32_t*)&Ah[base] = h0; *(uint32_t*)&Ah[base + 2] = h1;
            *(uint32_t*)&Al[base] = l0; *(uint32_t*)&Al[base + 2] = l1;
        }
    }
#pragma unroll
    for (int it = 0; it < LB; it++) {
        uint32_t h0, l0, h1, l1;
        bfsplit2(pb[it].x, pb[it].y, h0, l0);
        bfsplit2(pb[it].z, pb[it].w, h1, l1);
        int base = br[it] * BST + bc[it];
        *(uint32_t*)&Bh[base] = h0; *(uint32_t*)&Bh[base + 2] = h1;
        *(uint32_t*)&Bl[base] = l0; *(uint32_t*)&Bl[base + 2] = l1;
    }

    for (int k0 = 0; k0 < K; k0 += BK) {
        __syncthreads();
        bool more = (k0 + BK) < K;
        if (more) {
#pragma unroll
            for (int it = 0; it < LA; it++) {
                int gr = m0 + ar[it]; if (gr >= M) gr = M - 1;
                if (ASPLIT) {
                    pah[it] = *(const uint2*)(Ahg + (size_t)gr * K + k0 + BK + ac[it]);
                    pal[it] = *(const uint2*)(Alg + (size_t)gr * K + k0 + BK + ac[it]);
                } else {
                    pa[it] = *(const float4*)(A + (size_t)gr * K + k0 + BK + ac[it]);
                }
            }
#pragma unroll
            for (int it = 0; it < LB; it++)
                pb[it] = ldB<PERM>(B, N, k0 + BK + br[it], bc[it]);
        }
#pragma unroll
        for (int ks = 0; ks < BK / 16; ks++) {
            int kb = ks * 16;
            uint32_t af[MT][4], alf[MT][4];
#pragma unroll
            for (int mt = 0; mt < MT; mt++) {
                int mm = wm0 + mt * 16 + g;
                int base = mm * AST + kb + 2 * tig;
                af[mt][0]  = *(const uint32_t*)&Ah[base];
                af[mt][1]  = *(const uint32_t*)&Ah[base + 8 * AST];
                af[mt][2]  = *(const uint32_t*)&Ah[base + 8];
                af[mt][3]  = *(const uint32_t*)&Ah[base + 8 * AST + 8];
                alf[mt][0] = *(const uint32_t*)&Al[base];
                alf[mt][1] = *(const uint32_t*)&Al[base + 8 * AST];
                alf[mt][2] = *(const uint32_t*)&Al[base + 8];
                alf[mt][3] = *(const uint32_t*)&Al[base + 8 * AST + 8];
            }
            uint32_t bf[NT][2], blf[NT][2];
            int krow = kb + (lane & 15);
#pragma unroll
            for (int nt = 0; nt < NT; nt++) {
                uint32_t off = (uint32_t)((krow * BST + wn0 + nt * 8) * 2);
                ldmx2t(bf[nt][0], bf[nt][1], bh_u32 + off);
                ldmx2t(blf[nt][0], blf[nt][1], bl_u32 + off);
            }
#pragma unroll
            for (int mt = 0; mt < MT; mt++)
#pragma unroll
                for (int nt = 0; nt < NT; nt++) {
                    mma16816(c[mt][nt], alf[mt], bf[nt]);
                    mma16816(c[mt][nt], af[mt], blf[nt]);
                    mma16816(c[mt][nt], af[mt], bf[nt]);
                }
        }
        __syncthreads();
        if (more) {
#pragma unroll
            for (int it = 0; it < LA; it++) {
                int base = ar[it] * AST + ac[it];
                if (ASPLIT) {
                    *(uint32_t*)&Ah[base] = pah[it].x; *(uint32_t*)&Ah[base + 2] = pah[it].y;
                    *(uint32_t*)&Al[base] = pal[it].x; *(uint32_t*)&Al[base + 2] = pal[it].y;
                } else {
                    uint32_t h0, l0, h1, l1;
                    bfsplit2(pa[it].x, pa[it].y, h0, l0);
                    bfsplit2(pa[it].z, pa[it].w, h1, l1);
                    *(uint32_t*)&Ah[base] = h0; *(uint32_t*)&Ah[base + 2] = h1;
                    *(uint32_t*)&Al[base] = l0; *(uint32_t*)&Al[base + 2] = l1;
                }
            }
#pragma unroll
            for (int it = 0; it < LB; it++) {
                uint32_t h0, l0, h1, l1;
                bfsplit2(pb[it].x, pb[it].y, h0, l0);
                bfsplit2(pb[it].z, pb[it].w, h1, l1);
                int base = br[it] * BST + bc[it];
                *(uint32_t*)&Bh[base] = h0; *(uint32_t*)&Bh[base + 2] = h1;
                *(uint32_t*)&Bl[base] = l0; *(uint32_t*)&Bl[base + 2] = l1;
            }
        }
    }

    // C-store epilogue (fp16)
#pragma unroll
    for (int mt = 0; mt < MT; mt++) {
        int r0 = m0 + wm0 + mt * 16 + g;
        int r1 = r0 + 8;
#pragma unroll
        for (int nt = 0; nt < NT; nt++) {
            int cc = wn0 + nt * 8 + 2 * tig;
            if (r0 < M) *(__half2*)(Ch + (size_t)r0 * N + cc) =
                __floats2half2_rn(c[mt][nt][0], c[mt][nt][1]);
            if (r1 < M) *(__half2*)(Ch + (size_t)r1 * N + cc) =
                __floats2half2_rn(c[mt][nt][2], c[mt][nt][3]);
        }
    }

    if (EPI == 1) {
        int hd = wn0 >> 5;
        const float* as = av + hd * 64;
        const float* ad = as + 32;
#pragma unroll
        for (int mt = 0; mt < MT; mt++) {
            float es0 = 0.f, ed0 = 0.f, es1 = 0.f, ed1 = 0.f;
#pragma unroll
            for (int nt = 0; nt < NT; nt++) {
                int o = nt * 8 + 2 * tig;
                float a0 = as[o], a1v = as[o + 1];
                float d0 = ad[o], d1v = ad[o + 1];
                es0 += c[mt][nt][0] * a0 + c[mt][nt][1] * a1v;
                ed0 += c[mt][nt][0] * d0 + c[mt][nt][1] * d1v;
                es1 += c[mt][nt][2] * a0 + c[mt][nt][3] * a1v;
                ed1 += c[mt][nt][2] * d0 + c[mt][nt][3] * d1v;
            }
            es0 += __shfl_xor_sync(~0u, es0, 1); es0 += __shfl_xor_sync(~0u, es0, 2);
            ed0 += __shfl_xor_sync(~0u, ed0, 1); ed0 += __shfl_xor_sync(~0u, ed0, 2);
            es1 += __shfl_xor_sync(~0u, es1, 1); es1 += __shfl_xor_sync(~0u, es1, 2);
            ed1 += __shfl_xor_sync(~0u, ed1, 1); ed1 += __shfl_xor_sync(~0u, ed1, 2);
            if (tig == 0) {
                int r0 = m0 + wm0 + mt * 16 + g, r1 = r0 + 8;
                if (r0 < M) { g_es1[r0 * 4 + hd] = es0; g_ed1[r0 * 4 + hd] = ed0; }
                if (r1 < M) { g_es1[r1 * 4 + hd] = es1; g_ed1[r1 * 4 + hd] = ed1; }
            }
        }
    }
    if (EPI == 2) {
        int wn = warp % WARPS_N;
#pragma unroll
        for (int mt = 0; mt < MT; mt++) {
            float es0 = 0.f, ed0 = 0.f, es1 = 0.f, ed1 = 0.f;
#pragma unroll
            for (int nt = 0; nt < NT; nt++) {
                int o = wn0 + nt * 8 + 2 * tig;
                float a0 = av[o], a1v = av[o + 1];
                float d0 = av[64 + o], d1v = av[64 + o + 1];
                es0 += c[mt][nt][0] * a0 + c[mt][nt][1] * a1v;
                ed0 += c[mt][nt][0] * d0 + c[mt][nt][1] * d1v;
                es1 += c[mt][nt][2] * a0 + c[mt][nt][3] * a1v;
                ed1 += c[mt][nt][2] * d0 + c[mt][nt][3] * d1v;
            }
            es0 += __shfl_xor_sync(~0u, es0, 1); es0 += __shfl_xor_sync(~0u, es0, 2);
            ed0 += __shfl_xor_sync(~0u, ed0, 1); ed0 += __shfl_xor_sync(~0u, ed0, 2);
            es1 += __shfl_xor_sync(~0u, es1, 1); es1 += __shfl_xor_sync(~0u, es1, 2);
            ed1 += __shfl_xor_sync(~0u, ed1, 1); ed1 += __shfl_xor_sync(~0u, ed1, 2);
            if (tig == 0) {
                int rl0 = wm0 + mt * 16 + g, rl1 = rl0 + 8;
                s_red[(wn * BM + rl0) * 2 + 0] = es0;
                s_red[(wn * BM + rl0) * 2 + 1] = ed0;
                s_red[(wn * BM + rl1) * 2 + 0] = es1;
                s_red[(wn * BM + rl1) * 2 + 1] = ed1;
            }
        }
        __syncthreads();
        if (tid < BM) {
            int r = m0 + tid;
            if (r < M) {
                g_es2[r] = s_red[tid * 2 + 0] + s_red[(BM + tid) * 2 + 0];
                g_ed2[r] = s_red[tid * 2 + 1] + s_red[(BM + tid) * 2 + 1];
            }
        }
    }
}

// ------------------------- fused softmax + aggregate, layer 1 (R10-proven) ----
__global__ __launch_bounds__(256) void agg1_k() {
    __shared__ float2 sm_sw[8][4][33];   // [warp][head][j] = (src bits, w_h)
    int ws   = threadIdx.x >> 5;
    int node = blockIdx.x * 8 + ws;
    int lane = threadIdx.x & 31;
    if (node >= NN) return;
    unsigned long long acc01 = pack2(0.f, 0.f), acc23 = pack2(0.f, 0.f);
    int cnt = g_cnt[node];
    if (cnt > CAP) cnt = CAP;
    int h = lane >> 3;
    if (cnt > 0) {
        const int* slots = g_slots + (size_t)node * CAP;
        float4 ed4 = *(const float4*)(g_ed1 + node * 4);
        if (cnt <= 32) {
            bool act = lane < cnt;
            int s = act ? slots[lane] : 0;
            float4 w = make_float4(0.f, 0.f, 0.f, 0.f);
            if (act) {
                float4 a = *(const float4*)(g_es1 + s * 4);
                w.x = __expf(lrelu(a.x + ed4.x)); w.y = __expf(lrelu(a.y + ed4.y));
                w.z = __expf(lrelu(a.z + ed4.z)); w.w = __expf(lrelu(a.w + ed4.w));
            }
            float4 sum = w;
#pragma unroll
            for (int o = 16; o; o >>= 1) {
                sum.x += __shfl_xor_sync(~0u, sum.x, o);
                sum.y += __shfl_xor_sync(~0u, sum.y, o);
                sum.z += __shfl_xor_sync(~0u, sum.z, o);
                sum.w += __shfl_xor_sync(~0u, sum.w, o);
            }
            float sb = __int_as_float(s);
            sm_sw[ws][0][lane] = make_float2(sb, w.x * (1.f / sum.x));
            sm_sw[ws][1][lane] = make_float2(sb, w.y * (1.f / sum.y));
            sm_sw[ws][2][lane] = make_float2(sb, w.z * (1.f / sum.z));
            sm_sw[ws][3][lane] = make_float2(sb, w.w * (1.f / sum.w));
            __syncwarp();
#pragma unroll 4
            for (int j = 0; j < cnt; j++) {
                float2 sw = sm_sw[ws][h][j];
                int sj = __float_as_int(sw.x);
                unsigned long long w2 = pack2(sw.y, sw.y);
                uint2 zz = *(const uint2*)(g_z1h + ((size_t)sj << 7) + (lane << 2));
                float2 f0 = __half22float2(*(const __half2*)&zz.x);
                float2 f1 = __half22float2(*(const __half2*)&zz.y);
                ffma2(acc01, pack2(f0.x, f0.y), w2);
                ffma2(acc23, pack2(f1.x, f1.y), w2);
            }
        } else {
            float4 sum = make_float4(0.f, 0.f, 0.f, 0.f);
            for (int base = 0; base < cnt; base += 32) {
                if (base + lane < cnt) {
                    int s = slots[base + lane];
                    float4 a = *(const float4*)(g_es1 + s * 4);
                    sum.x += __expf(lrelu(a.x + ed4.x));
                    sum.y += __expf(lrelu(a.y + ed4.y));
                    sum.z += __expf(lrelu(a.z + ed4.z));
                    sum.w += __expf(lrelu(a.w + ed4.w));
                }
            }
#pragma unroll
            for (int o = 16; o; o >>= 1) {
                sum.x += __shfl_xor_sync(~0u, sum.x, o);
                sum.y += __shfl_xor_sync(~0u, sum.y, o);
                sum.z += __shfl_xor_sync(~0u, sum.z, o);
                sum.w += __shfl_xor_sync(~0u, sum.w, o);
            }
            float4 inv = make_float4(1.f / sum.x, 1.f / sum.y, 1.f / sum.z, 1.f / sum.w);
            for (int base = 0; base < cnt; base += 32) {
                int n = min(32, cnt - base);
                if (lane < n) {
                    int s = slots[base + lane];
                    float4 a = *(const float4*)(g_es1 + s * 4);
                    float sb = __int_as_float(s);
                    sm_sw[ws][0][lane] = make_float2(sb, __expf(lrelu(a.x + ed4.x)) * inv.x);
                    sm_sw[ws][1][lane] = make_float2(sb, __expf(lrelu(a.y + ed4.y)) * inv.y);
                    sm_sw[ws][2][lane] = make_float2(sb, __expf(lrelu(a.z + ed4.z)) * inv.z);
                    sm_sw[ws][3][lane] = make_float2(sb, __expf(lrelu(a.w + ed4.w)) * inv.w);
                }
                __syncwarp();
#pragma unroll 4
                for (int j = 0; j < n; j++) {
                    float2 sw = sm_sw[ws][h][j];
                    int sj = __float_as_int(sw.x);
                    unsigned long long w2 = pack2(sw.y, sw.y);
                    uint2 zz = *(const uint2*)(g_z1h + ((size_t)sj << 7) + (lane << 2));
                    float2 f0 = __half22float2(*(const __half2*)&zz.x);
                    float2 f1 = __half22float2(*(const __half2*)&zz.y);
                    ffma2(acc01, pack2(f0.x, f0.y), w2);
                    ffma2(acc23, pack2(f1.x, f1.y), w2);
                }
                __syncwarp();
            }
        }
    }
    float ax, ay, az, aw;
    unpack2(acc01, ax, ay);
    unpack2(acc23, az, aw);
    float4 o;
    o.x = ax > 0.f ? ax : expm1f(ax);
    o.y = ay > 0.f ? ay : expm1f(ay);
    o.z = az > 0.f ? az : expm1f(az);
    o.w = aw > 0.f ? aw : expm1f(aw);
    // store pre-split bf16 hi/lo planes (GEMM2 A operand)
    uint32_t h0, l0, h1, l1;
    bfsplit2(o.x, o.y, h0, l0);
    bfsplit2(o.z, o.w, h1, l1);
    size_t idx = (size_t)node * D1 + lane * 4;
    *(uint2*)&g_h1h[idx] = make_uint2(h0, h1);
    *(uint2*)&g_h1l[idx] = make_uint2(l0, l1);
}

// ------------------------- fused softmax + aggregate, layer 2 (R10-proven) ----
__global__ __launch_bounds__(256) void agg2_k(float* __restrict__ out) {
    __shared__ float2 sm_sw[8][33];
    int ws   = threadIdx.x >> 5;
    int node = blockIdx.x * 8 + ws;
    int lane = threadIdx.x & 31;
    if (node >= NN) return;
    unsigned long long acc = pack2(0.f, 0.f);
    int cnt = g_cnt[node];
    if (cnt > CAP) cnt = CAP;
    if (cnt > 0) {
        const int* slots = g_slots + (size_t)node * CAP;
        float edv = g_ed2[node];
        if (cnt <= 32) {
            bool act = lane < cnt;
            int s = act ? slots[lane] : 0;
            float w = act ? __expf(lrelu(g_es2[s] + edv)) : 0.f;
            float sum = w;
#pragma unroll
            for (int o = 16; o; o >>= 1) sum += __shfl_xor_sync(~0u, sum, o);
            sm_sw[ws][lane] = make_float2(__int_as_float(s), w * (1.f / sum));
            __syncwarp();
#pragma unroll 4
            for (int j = 0; j < cnt; j++) {
                float2 sw = sm_sw[ws][j];
                int sj = __float_as_int(sw.x);
                unsigned long long w2 = pack2(sw.y, sw.y);
                __half2 zh = *(const __half2*)(g_z2h + ((size_t)sj << 6) + (lane << 1));
                float2 f = __half22float2(zh);
                ffma2(acc, pack2(f.x, f.y), w2);
            }
        } else {
            float sum = 0.f;
            for (int base = 0; base < cnt; base += 32)
                if (base + lane < cnt)
                    sum += __expf(lrelu(g_es2[slots[base + lane]] + edv));
#pragma unroll
            for (int o = 16; o; o >>= 1) sum += __shfl_xor_sync(~0u, sum, o);
            float inv = 1.f / sum;
            for (int base = 0; base < cnt; base += 32) {
                int n = min(32, cnt - base);
                if (lane < n) {
                    int s = slots[base + lane];
                    sm_sw[ws][lane] = make_float2(__int_as_float(s),
                                                  __expf(lrelu(g_es2[s] + edv)) * inv);
                }
                __syncwarp();
#pragma unroll 4
                for (int j = 0; j < n; j++) {
                    float2 sw = sm_sw[ws][j];
                    int sj = __float_as_int(sw.x);
                    unsigned long long w2 = pack2(sw.y, sw.y);
                    __half2 zh = *(const __half2*)(g_z2h + ((size_t)sj << 6) + (lane << 1));
                    float2 f = __half22float2(zh);
                    ffma2(acc, pack2(f.x, f.y), w2);
                }
                __syncwarp();
            }
        }
    }
    float ax, ay;
    unpack2(acc, ax, ay);
    *(float2*)(out + (size_t)node * D2 + lane * 2) = make_float2(ax, ay);
    // self-cleaning counter: next launch's fill_k needs zeros
    if (lane == 0) g_cnt[node] = 0;
}

// ------------------------- launch -------------------------
extern "C" void kernel_launch(void* const* d_in, const int* in_sizes, int n_in,
                              void* d_out, int out_size) {
    const float* h   = (const float*)d_in[0];
    const int*   src = (const int*)d_in[1];
    const int*   dst = (const int*)d_in[2];
    const float* W1  = (const float*)d_in[3];
    const float* a1  = (const float*)d_in[4];
    const float* W2  = (const float*)d_in[5];
    const float* a2  = (const float*)d_in[6];
    float* out = (float*)d_out;

    void *pz1h, *ph1h, *ph1l, *pz2h;
    cudaGetSymbolAddress(&pz1h, g_z1h);
    cudaGetSymbolAddress(&ph1h, g_h1h);
    cudaGetSymbolAddress(&ph1l, g_h1l);
    cudaGetSymbolAddress(&pz2h, g_z2h);

    int nwb = (NN + 7) / 8;
    int mblocks = (NN + 127) / 128;

    // fork: slot-table build on side stream, concurrent with gemm1
    cudaStream_t side;
    cudaStreamCreateWithFlags(&side, cudaStreamNonBlocking);
    cudaEvent_t evRoot, evCsr;
    cudaEventCreateWithFlags(&evRoot, cudaEventDisableTiming);
    cudaEventCreateWithFlags(&evCsr, cudaEventDisableTiming);

    cudaEventRecord(evRoot, 0);
    cudaStreamWaitEvent(side, evRoot, 0);
    fill_k<<<(NE + 255) / 256, 256, 0, side>>>(src, dst);
    cudaEventRecord(evCsr, side);

    // layer 1: projection + fused es/ed epilogue (z1 stored fp16)
    mma_gemm<128, 128, 32, 2, 4, true, 1, false><<<mblocks, 256>>>(
        h, nullptr, nullptr, W1, (__half*)pz1h, a1, NN, D1, IND);

    cudaStreamWaitEvent(0, evCsr, 0);   // join
    agg1_k<<<nwb, 256>>>();

    // layer 2: projection (A = pre-split bf16 planes) + fused es/ed epilogue
    mma_gemm<128, 64, 32, 2, 2, false, 2, true><<<mblocks, 128>>>(
        nullptr, (const uint16_t*)ph1h, (const uint16_t*)ph1l, W2,
        (__half*)pz2h, a2, NN, D2, D1);
    agg2_k<<<nwb, 256>>>(out);
}

// round 13
// speedup vs baseline: 1.0224x; 1.0224x over previous
#include <cuda_runtime.h>
#include <cuda_fp16.h>
#include <math.h>
#include <stdint.h>

#define NN   50000
#define NE   800000
#define IND  256
#define D1   128   // HEADS*HIDDEN
#define D2   64    // OUT_DIM
#define CAP  128   // max in-degree capacity (Poisson(16) max ~50; 128 is safe)

// ------------------------- device scratch (no allocs) -------------------------
__device__ __half g_z1h[(size_t)NN * D1];    // layer-1 projections (fp16, gather-only)
__device__ float  g_h1[(size_t)NN * D1];     // elu(layer-1 out), fp32
__device__ __half g_z2h[(size_t)NN * D2];    // layer-2 projections (fp16, gather-only)
__device__ float g_es1[NN * 4], g_ed1[NN * 4];
__device__ float g_es2[NN],     g_ed2[NN];
__device__ int   g_cnt[NN];                  // in-degree (self-cleaning: agg2 re-zeros)
__device__ int   g_slots[(size_t)NN * CAP];  // src lists per dst (slot table)

__device__ __forceinline__ float lrelu(float x) { return x > 0.f ? x : 0.01f * x; }

// packed f32x2 helpers (Blackwell dual-FMA)
__device__ __forceinline__ unsigned long long pack2(float x, float y) {
    unsigned long long r;
    asm("mov.b64 %0, {%1, %2};" : "=l"(r) : "f"(x), "f"(y));
    return r;
}
__device__ __forceinline__ void unpack2(unsigned long long v, float& x, float& y) {
    asm("mov.b64 {%0, %1}, %2;" : "=f"(x), "=f"(y) : "l"(v));
}
__device__ __forceinline__ void ffma2(unsigned long long& acc,
                                      unsigned long long a, unsigned long long b) {
    asm("fma.rn.f32x2 %0, %1, %2, %0;" : "+l"(acc) : "l"(a), "l"(b));
}

// ------------------------- slot-table build -------------------------
__global__ void fill_k(const int* __restrict__ src, const int* __restrict__ dst) {
    int e = blockIdx.x * blockDim.x + threadIdx.x;
    if (e >= NE) return;
    int d = dst[e];
    int pos = atomicAdd(&g_cnt[d], 1);
    if (pos < CAP) g_slots[(size_t)d * CAP + pos] = src[e];
}

// ------------------------- bf16 3-term split GEMM (tensor core) -------------
__device__ __forceinline__ void bfsplit2(float x, float y, uint32_t& hi, uint32_t& lo) {
    asm("cvt.rn.bf16x2.f32 %0, %1, %2;" : "=r"(hi) : "f"(y), "f"(x));
    float hx = __uint_as_float(hi << 16);
    float hy = __uint_as_float(hi & 0xFFFF0000u);
    float lx = x - hx, ly = y - hy;
    asm("cvt.rn.bf16x2.f32 %0, %1, %2;" : "=r"(lo) : "f"(ly), "f"(lx));
}

__device__ __forceinline__ void ldmx2t(uint32_t& r0, uint32_t& r1, uint32_t addr) {
    asm volatile("ldmatrix.sync.aligned.m8n8.x2.trans.shared.b16 {%0,%1}, [%2];"
                 : "=r"(r0), "=r"(r1) : "r"(addr));
}

__device__ __forceinline__ void mma16816(float c[4], const uint32_t a[4],
                                         const uint32_t b[2]) {
    asm volatile(
        "mma.sync.aligned.m16n8k16.row.col.f32.bf16.bf16.f32 "
        "{%0,%1,%2,%3}, {%4,%5,%6,%7}, {%8,%9}, {%0,%1,%2,%3};"
        : "+f"(c[0]), "+f"(c[1]), "+f"(c[2]), "+f"(c[3])
        : "r"(a[0]), "r"(a[1]), "r"(a[2]), "r"(a[3]), "r"(b[0]), "r"(b[1]));
}

template <bool PERM>
__device__ __forceinline__ float4 ldB(const float* __restrict__ B, int N,
                                      int row, int col) {
    if (PERM) {
        int h = col >> 5, o = col & 31;
        return *(const float4*)(B + h * (IND * 32) + row * 32 + o);
    }
    return *(const float4*)(B + (size_t)row * N + col);
}

// C[M,N] = A[M,K] * B[K,N], row-major; C stored fp16 (gather-only consumer).
// Warp tile WM=BM/WARPS_M (32 here -> 32 accum regs), WN=BN/WARPS_N (must be 32).
// EPI==1: fused 4-head es/ed epilogue. EPI==2: single-head es/ed (smem join).
template <int BM, int BN, int BK, int WARPS_M, int WARPS_N, bool PERM, int EPI>
__global__ __launch_bounds__(WARPS_M * WARPS_N * 32, 1)
void mma_gemm(const float* __restrict__ A, const float* __restrict__ B,
              __half* __restrict__ Ch, const float* __restrict__ av,
              int M, int N, int K) {
    constexpr int WM = BM / WARPS_M, WN = BN / WARPS_N;
    static_assert(WN == 32, "EPI epilogues require WN==32");
    constexpr int MT = WM / 16, NT = WN / 8;
    constexpr int THREADS = WARPS_M * WARPS_N * 32;
    constexpr int LA = BM * BK / 4 / THREADS;
    constexpr int LB = BK * BN / 4 / THREADS;
    constexpr int AST = BK + 8;
    constexpr int BST = BN + 8;

    __shared__ alignas(16) uint16_t Ah[BM * AST], Al[BM * AST];
    __shared__ alignas(16) uint16_t Bh[BK * BST], Bl[BK * BST];
    __shared__ float s_red[(EPI == 2) ? 2 * BM * 2 : 1];

    int tid  = threadIdx.x;
    int warp = tid >> 5, lane = tid & 31;
    int g = lane >> 2, tig = lane & 3;
    int wm0 = (warp / WARPS_N) * WM;
    int wn0 = (warp % WARPS_N) * WN;
    int m0  = blockIdx.x * BM;

    uint32_t bh_u32 = (uint32_t)__cvta_generic_to_shared(Bh);
    uint32_t bl_u32 = (uint32_t)__cvta_generic_to_shared(Bl);

    float c[MT][NT][4];
#pragma unroll
    for (int i = 0; i < MT; i++)
#pragma unroll
        for (int j = 0; j < NT; j++)
#pragma unroll
            for (int v = 0; v < 4; v++) c[i][j][v] = 0.f;

    float4 pa[LA], pb[LB];
    int ar[LA], ac[LA], br[LB], bc[LB];
#pragma unroll
    for (int it = 0; it < LA; it++) {
        int i = it * THREADS + tid;
        ar[it] = i / (BK / 4);
        ac[it] = (i % (BK / 4)) * 4;
    }
#pragma unroll
    for (int it = 0; it < LB; it++) {
        int i = it * THREADS + tid;
        br[it] = i / (BN / 4);
        bc[it] = (i % (BN / 4)) * 4;
    }

#pragma unroll
    for (int it = 0; it < LA; it++) {
        int gr = m0 + ar[it]; if (gr >= M) gr = M - 1;
        pa[it] = *(const float4*)(A + (size_t)gr * K + ac[it]);
    }
#pragma unroll
    for (int it = 0; it < LB; it++)
        pb[it] = ldB<PERM>(B, N, br[it], bc[it]);
#pragma unroll
    for (int it = 0; it < LA; it++) {
        uint32_t h0, l0, h1, l1;
        bfsplit2(pa[it].x, pa[it].y, h0, l0);
        bfsplit2(pa[it].z, pa[it].w, h1, l1);
        int base = ar[it] * AST + ac[it];
        *(uint32_t*)&Ah[base] = h0; *(uint32_t*)&Ah[base + 2] = h1;
        *(uint32_t*)&Al[base] = l0; *(uint32_t*)&Al[base + 2] = l1;
    }
#pragma unroll
    for (int it = 0; it < LB; it++) {
        uint32_t h0, l0, h1, l1;
        bfsplit2(pb[it].x, pb[it].y, h0, l0);
        bfsplit2(pb[it].z, pb[it].w, h1, l1);
        int base = br[it] * BST + bc[it];
        *(uint32_t*)&Bh[base] = h0; *(uint32_t*)&Bh[base + 2] = h1;
        *(uint32_t*)&Bl[base] = l0; *(uint32_t*)&Bl[base + 2] = l1;
    }

    for (int k0 = 0; k0 < K; k0 += BK) {
        __syncthreads();
        bool more = (k0 + BK) < K;
        if (more) {
#pragma unroll
            for (int it = 0; it < LA; it++) {
                int gr = m0 + ar[it]; if (gr >= M) gr = M - 1;
                pa[it] = *(const float4*)(A + (size_t)gr * K + k0 + BK + ac[it]);
            }
#pragma unroll
            for (int it = 0; it < LB; it++)
                pb[it] = ldB<PERM>(B, N, k0 + BK + br[it], bc[it]);
        }
#pragma unroll
        for (int ks = 0; ks < BK / 16; ks++) {
            int kb = ks * 16;
            uint32_t af[MT][4], alf[MT][4];
#pragma unroll
            for (int mt = 0; mt < MT; mt++) {
                int mm = wm0 + mt * 16 + g;
                int base = mm * AST + kb + 2 * tig;
                af[mt][0]  = *(const uint32_t*)&Ah[base];
                af[mt][1]  = *(const uint32_t*)&Ah[base + 8 * AST];
                af[mt][2]  = *(const uint32_t*)&Ah[base + 8];
                af[mt][3]  = *(const uint32_t*)&Ah[base + 8 * AST + 8];
                alf[mt][0] = *(const uint32_t*)&Al[base];
                alf[mt][1] = *(const uint32_t*)&Al[base + 8 * AST];
                alf[mt][2] = *(const uint32_t*)&Al[base + 8];
                alf[mt][3] = *(const uint32_t*)&Al[base + 8 * AST + 8];
            }
            uint32_t bf[NT][2], blf[NT][2];
            int krow = kb + (lane & 15);
#pragma unroll
            for (int nt = 0; nt < NT; nt++) {
                uint32_t off = (uint32_t)((krow * BST + wn0 + nt * 8) * 2);
                ldmx2t(bf[nt][0], bf[nt][1], bh_u32 + off);
                ldmx2t(blf[nt][0], blf[nt][1], bl_u32 + off);
            }
#pragma unroll
            for (int mt = 0; mt < MT; mt++)
#pragma unroll
                for (int nt = 0; nt < NT; nt++) {
                    mma16816(c[mt][nt], alf[mt], bf[nt]);
                    mma16816(c[mt][nt], af[mt], blf[nt]);
                    mma16816(c[mt][nt], af[mt], bf[nt]);
                }
        }
        __syncthreads();
        if (more) {
#pragma unroll
            for (int it = 0; it < LA; it++) {
                uint32_t h0, l0, h1, l1;
                bfsplit2(pa[it].x, pa[it].y, h0, l0);
                bfsplit2(pa[it].z, pa[it].w, h1, l1);
                int base = ar[it] * AST + ac[it];
                *(uint32_t*)&Ah[base] = h0; *(uint32_t*)&Ah[base + 2] = h1;
                *(uint32_t*)&Al[base] = l0; *(uint32_t*)&Al[base + 2] = l1;
            }
#pragma unroll
            for (int it = 0; it < LB; it++) {
                uint32_t h0, l0, h1, l1;
                bfsplit2(pb[it].x, pb[it].y, h0, l0);
                bfsplit2(pb[it].z, pb[it].w, h1, l1);
                int base = br[it] * BST + bc[it];
                *(uint32_t*)&Bh[base] = h0; *(uint32_t*)&Bh[base + 2] = h1;
                *(uint32_t*)&Bl[base] = l0; *(uint32_t*)&Bl[base + 2] = l1;
            }
        }
    }

    // C-store epilogue (fp16)
#pragma unroll
    for (int mt = 0; mt < MT; mt++) {
        int r0 = m0 + wm0 + mt * 16 + g;
        int r1 = r0 + 8;
#pragma unroll
        for (int nt = 0; nt < NT; nt++) {
            int cc = wn0 + nt * 8 + 2 * tig;
            if (r0 < M) *(__half2*)(Ch + (size_t)r0 * N + cc) =
                __floats2half2_rn(c[mt][nt][0], c[mt][nt][1]);
            if (r1 < M) *(__half2*)(Ch + (size_t)r1 * N + cc) =
                __floats2half2_rn(c[mt][nt][2], c[mt][nt][3]);
        }
    }

    if (EPI == 1) {
        int hd = wn0 >> 5;
        const float* as = av + hd * 64;
        const float* ad = as + 32;
#pragma unroll
        for (int mt = 0; mt < MT; mt++) {
            float es0 = 0.f, ed0 = 0.f, es1 = 0.f, ed1 = 0.f;
#pragma unroll
            for (int nt = 0; nt < NT; nt++) {
                int o = nt * 8 + 2 * tig;
                float a0 = as[o], a1v = as[o + 1];
                float d0 = ad[o], d1v = ad[o + 1];
                es0 += c[mt][nt][0] * a0 + c[mt][nt][1] * a1v;
                ed0 += c[mt][nt][0] * d0 + c[mt][nt][1] * d1v;
                es1 += c[mt][nt][2] * a0 + c[mt][nt][3] * a1v;
                ed1 += c[mt][nt][2] * d0 + c[mt][nt][3] * d1v;
            }
            es0 += __shfl_xor_sync(~0u, es0, 1); es0 += __shfl_xor_sync(~0u, es0, 2);
            ed0 += __shfl_xor_sync(~0u, ed0, 1); ed0 += __shfl_xor_sync(~0u, ed0, 2);
            es1 += __shfl_xor_sync(~0u, es1, 1); es1 += __shfl_xor_sync(~0u, es1, 2);
            ed1 += __shfl_xor_sync(~0u, ed1, 1); ed1 += __shfl_xor_sync(~0u, ed1, 2);
            if (tig == 0) {
                int r0 = m0 + wm0 + mt * 16 + g, r1 = r0 + 8;
                if (r0 < M) { g_es1[r0 * 4 + hd] = es0; g_ed1[r0 * 4 + hd] = ed0; }
                if (r1 < M) { g_es1[r1 * 4 + hd] = es1; g_ed1[r1 * 4 + hd] = ed1; }
            }
        }
    }
    if (EPI == 2) {
        int wn = warp % WARPS_N;
#pragma unroll
        for (int mt = 0; mt < MT; mt++) {
            float es0 = 0.f, ed0 = 0.f, es1 = 0.f, ed1 = 0.f;
#pragma unroll
            for (int nt = 0; nt < NT; nt++) {
                int o = wn0 + nt * 8 + 2 * tig;
                float a0 = av[o], a1v = av[o + 1];
                float d0 = av[64 + o], d1v = av[64 + o + 1];
                es0 += c[mt][nt][0] * a0 + c[mt][nt][1] * a1v;
                ed0 += c[mt][nt][0] * d0 + c[mt][nt][1] * d1v;
                es1 += c[mt][nt][2] * a0 + c[mt][nt][3] * a1v;
                ed1 += c[mt][nt][2] * d0 + c[mt][nt][3] * d1v;
            }
            es0 += __shfl_xor_sync(~0u, es0, 1); es0 += __shfl_xor_sync(~0u, es0, 2);
            ed0 += __shfl_xor_sync(~0u, ed0, 1); ed0 += __shfl_xor_sync(~0u, ed0, 2);
            es1 += __shfl_xor_sync(~0u, es1, 1); es1 += __shfl_xor_sync(~0u, es1, 2);
            ed1 += __shfl_xor_sync(~0u, ed1, 1); ed1 += __shfl_xor_sync(~0u, ed1, 2);
            if (tig == 0) {
                int rl0 = wm0 + mt * 16 + g, rl1 = rl0 + 8;
                s_red[(wn * BM + rl0) * 2 + 0] = es0;
                s_red[(wn * BM + rl0) * 2 + 1] = ed0;
                s_red[(wn * BM + rl1) * 2 + 0] = es1;
                s_red[(wn * BM + rl1) * 2 + 1] = ed1;
            }
        }
        __syncthreads();
        if (tid < BM) {
            int r = m0 + tid;
            if (r < M) {
                g_es2[r] = s_red[tid * 2 + 0] + s_red[(BM + tid) * 2 + 0];
                g_ed2[r] = s_red[tid * 2 + 1] + s_red[(BM + tid) * 2 + 1];
            }
        }
    }
}

// ------------------------- fused softmax + aggregate, layer 1 (R10-proven) ----
__global__ __launch_bounds__(256) void agg1_k() {
    __shared__ float2 sm_sw[8][4][33];   // [warp][head][j] = (src bits, w_h)
    int ws   = threadIdx.x >> 5;
    int node = blockIdx.x * 8 + ws;
    int lane = threadIdx.x & 31;
    if (node >= NN) return;
    unsigned long long acc01 = pack2(0.f, 0.f), acc23 = pack2(0.f, 0.f);
    int cnt = g_cnt[node];
    if (cnt > CAP) cnt = CAP;
    int h = lane >> 3;
    if (cnt > 0) {
        const int* slots = g_slots + (size_t)node * CAP;
        float4 ed4 = *(const float4*)(g_ed1 + node * 4);
        if (cnt <= 32) {
            bool act = lane < cnt;
            int s = act ? slots[lane] : 0;
            float4 w = make_float4(0.f, 0.f, 0.f, 0.f);
            if (act) {
                float4 a = *(const float4*)(g_es1 + s * 4);
                w.x = __expf(lrelu(a.x + ed4.x)); w.y = __expf(lrelu(a.y + ed4.y));
                w.z = __expf(lrelu(a.z + ed4.z)); w.w = __expf(lrelu(a.w + ed4.w));
            }
            float4 sum = w;
#pragma unroll
            for (int o = 16; o; o >>= 1) {
                sum.x += __shfl_xor_sync(~0u, sum.x, o);
                sum.y += __shfl_xor_sync(~0u, sum.y, o);
                sum.z += __shfl_xor_sync(~0u, sum.z, o);
                sum.w += __shfl_xor_sync(~0u, sum.w, o);
            }
            float sb = __int_as_float(s);
            sm_sw[ws][0][lane] = make_float2(sb, w.x * (1.f / sum.x));
            sm_sw[ws][1][lane] = make_float2(sb, w.y * (1.f / sum.y));
            sm_sw[ws][2][lane] = make_float2(sb, w.z * (1.f / sum.z));
            sm_sw[ws][3][lane] = make_float2(sb, w.w * (1.f / sum.w));
            __syncwarp();
#pragma unroll 4
            for (int j = 0; j < cnt; j++) {
                float2 sw = sm_sw[ws][h][j];
                int sj = __float_as_int(sw.x);
                unsigned long long w2 = pack2(sw.y, sw.y);
                uint2 zz = *(const uint2*)(g_z1h + ((size_t)sj << 7) + (lane << 2));
                float2 f0 = __half22float2(*(const __half2*)&zz.x);
                float2 f1 = __half22float2(*(const __half2*)&zz.y);
                ffma2(acc01, pack2(f0.x, f0.y), w2);
                ffma2(acc23, pack2(f1.x, f1.y), w2);
            }
        } else {
            float4 sum = make_float4(0.f, 0.f, 0.f, 0.f);
            for (int base = 0; base < cnt; base += 32) {
                if (base + lane < cnt) {
                    int s = slots[base + lane];
                    float4 a = *(const float4*)(g_es1 + s * 4);
                    sum.x += __expf(lrelu(a.x + ed4.x));
                    sum.y += __expf(lrelu(a.y + ed4.y));
                    sum.z += __expf(lrelu(a.z + ed4.z));
                    sum.w += __expf(lrelu(a.w + ed4.w));
                }
            }
#pragma unroll
            for (int o = 16; o; o >>= 1) {
                sum.x += __shfl_xor_sync(~0u, sum.x, o);
                sum.y += __shfl_xor_sync(~0u, sum.y, o);
                sum.z += __shfl_xor_sync(~0u, sum.z, o);
                sum.w += __shfl_xor_sync(~0u, sum.w, o);
            }
            float4 inv = make_float4(1.f / sum.x, 1.f / sum.y, 1.f / sum.z, 1.f / sum.w);
            for (int base = 0; base < cnt; base += 32) {
                int n = min(32, cnt - base);
                if (lane < n) {
                    int s = slots[base + lane];
                    float4 a = *(const float4*)(g_es1 + s * 4);
                    float sb = __int_as_float(s);
                    sm_sw[ws][0][lane] = make_float2(sb, __expf(lrelu(a.x + ed4.x)) * inv.x);
                    sm_sw[ws][1][lane] = make_float2(sb, __expf(lrelu(a.y + ed4.y)) * inv.y);
                    sm_sw[ws][2][lane] = make_float2(sb, __expf(lrelu(a.z + ed4.z)) * inv.z);
                    sm_sw[ws][3][lane] = make_float2(sb, __expf(lrelu(a.w + ed4.w)) * inv.w);
                }
                __syncwarp();
#pragma unroll 4
                for (int j = 0; j < n; j++) {
                    float2 sw = sm_sw[ws][h][j];
                    int sj = __float_as_int(sw.x);
                    unsigned long long w2 = pack2(sw.y, sw.y);
                    uint2 zz = *(const uint2*)(g_z1h + ((size_t)sj << 7) + (lane << 2));
                    float2 f0 = __half22float2(*(const __half2*)&zz.x);
                    float2 f1 = __half22float2(*(const __half2*)&zz.y);
                    ffma2(acc01, pack2(f0.x, f0.y), w2);
                    ffma2(acc23, pack2(f1.x, f1.y), w2);
                }
                __syncwarp();
            }
        }
    }
    float ax, ay, az, aw;
    unpack2(acc01, ax, ay);
    unpack2(acc23, az, aw);
    float4 o;
    o.x = ax > 0.f ? ax : expm1f(ax);
    o.y = ay > 0.f ? ay : expm1f(ay);
    o.z = az > 0.f ? az : expm1f(az);
    o.w = aw > 0.f ? aw : expm1f(aw);
    *(float4*)(g_h1 + (size_t)node * D1 + lane * 4) = o;
}

// ------------------------- fused softmax + aggregate, layer 2 (R10-proven) ----
__global__ __launch_bounds__(256) void agg2_k(float* __restrict__ out) {
    __shared__ float2 sm_sw[8][33];
    int ws   = threadIdx.x >> 5;
    int node = blockIdx.x * 8 + ws;
    int lane = threadIdx.x & 31;
    if (node >= NN) return;
    unsigned long long acc = pack2(0.f, 0.f);
    int cnt = g_cnt[node];
    if (cnt > CAP) cnt = CAP;
    if (cnt > 0) {
        const int* slots = g_slots + (size_t)node * CAP;
        float edv = g_ed2[node];
        if (cnt <= 32) {
            bool act = lane < cnt;
            int s = act ? slots[lane] : 0;
            float w = act ? __expf(lrelu(g_es2[s] + edv)) : 0.f;
            float sum = w;
#pragma unroll
            for (int o = 16; o; o >>= 1) sum += __shfl_xor_sync(~0u, sum, o);
            sm_sw[ws][lane] = make_float2(__int_as_float(s), w * (1.f / sum));
            __syncwarp();
#pragma unroll 4
            for (int j = 0; j < cnt; j++) {
                float2 sw = sm_sw[ws][j];
                int sj = __float_as_int(sw.x);
                unsigned long long w2 = pack2(sw.y, sw.y);
                __half2 zh = *(const __half2*)(g_z2h + ((size_t)sj << 6) + (lane << 1));
                float2 f = __half22float2(zh);
                ffma2(acc, pack2(f.x, f.y), w2);
            }
        } else {
            float sum = 0.f;
            for (int base = 0; base < cnt; base += 32)
                if (base + lane < cnt)
                    sum += __expf(lrelu(g_es2[slots[base + lane]] + edv));
#pragma unroll
            for (int o = 16; o; o >>= 1) sum += __shfl_xor_sync(~0u, sum, o);
            float inv = 1.f / sum;
            for (int base = 0; base < cnt; base += 32) {
                int n = min(32, cnt - base);
                if (lane < n) {
                    int s = slots[base + lane];
                    sm_sw[ws][lane] = make_float2(__int_as_float(s),
                                                  __expf(lrelu(g_es2[s] + edv)) * inv);
                }
                __syncwarp();
#pragma unroll 4
                for (int j = 0; j < n; j++) {
                    float2 sw = sm_sw[ws][j];
                    int sj = __float_as_int(sw.x);
                    unsigned long long w2 = pack2(sw.y, sw.y);
                    __half2 zh = *(const __half2*)(g_z2h + ((size_t)sj << 6) + (lane << 1));
                    float2 f = __half22float2(zh);
                    ffma2(acc, pack2(f.x, f.y), w2);
                }
                __syncwarp();
            }
        }
    }
    float ax, ay;
    unpack2(acc, ax, ay);
    *(float2*)(out + (size_t)node * D2 + lane * 2) = make_float2(ax, ay);
    // self-cleaning counter: next launch's fill_k needs zeros
    if (lane == 0) g_cnt[node] = 0;
}

// ------------------------- launch -------------------------
extern "C" void kernel_launch(void* const* d_in, const int* in_sizes, int n_in,
                              void* d_out, int out_size) {
    const float* h   = (const float*)d_in[0];
    const int*   src = (const int*)d_in[1];
    const int*   dst = (const int*)d_in[2];
    const float* W1  = (const float*)d_in[3];
    const float* a1  = (const float*)d_in[4];
    const float* W2  = (const float*)d_in[5];
    const float* a2  = (const float*)d_in[6];
    float* out = (float*)d_out;

    void *pz1h, *ph1, *pz2h;
    cudaGetSymbolAddress(&pz1h, g_z1h);
    cudaGetSymbolAddress(&ph1, g_h1);
    cudaGetSymbolAddress(&pz2h, g_z2h);

    int nwb = (NN + 7) / 8;
    int mblocks = (NN + 127) / 128;

    // fork: slot-table build on side stream, concurrent with gemm1
    cudaStream_t side;
    cudaStreamCreateWithFlags(&side, cudaStreamNonBlocking);
    cudaEvent_t evRoot, evCsr;
    cudaEventCreateWithFlags(&evRoot, cudaEventDisableTiming);
    cudaEventCreateWithFlags(&evCsr, cudaEventDisableTiming);

    cudaEventRecord(evRoot, 0);
    cudaStreamWaitEvent(side, evRoot, 0);
    fill_k<<<(NE + 255) / 256, 256, 0, side>>>(src, dst);
    cudaEventRecord(evCsr, side);

    // layer 1: WM=32 warp tile (4x4 warps, 512 threads) + fused es/ed epilogue
    mma_gemm<128, 128, 32, 4, 4, true, 1><<<mblocks, 512>>>(
        h, W1, (__half*)pz1h, a1, NN, D1, IND);

    cudaStreamWaitEvent(0, evCsr, 0);   // join
    agg1_k<<<nwb, 256>>>();

    // layer 2: WM=32 warp tile (4x2 warps, 256 threads) + fused es/ed epilogue
    mma_gemm<128, 64, 32, 4, 2, false, 2><<<mblocks, 256>>>(
        (const float*)ph1, W2, (__half*)pz2h, a2, NN, D2, D1);
    agg2_k<<<nwb, 256>>>(out);
}

// round 14
// speedup vs baseline: 1.0306x; 1.0080x over previous
#include <cuda_runtime.h>
#include <cuda_fp16.h>
#include <math.h>
#include <stdint.h>

#define NN   50000
#define NE   800000
#define IND  256
#define D1   128   // HEADS*HIDDEN
#define D2   64    // OUT_DIM
#define CAP  128   // max in-degree capacity (Poisson(16) max ~50; 128 is safe)

// ------------------------- device scratch (no allocs) -------------------------
__device__ __half g_z1h[(size_t)NN * D1];    // layer-1 projections (fp16, gather-only)
__device__ __half g_h1h[(size_t)NN * D1];    // elu(layer-1 out), fp16
__device__ __half g_z2h[(size_t)NN * D2];    // layer-2 projections (fp16, gather-only)
__device__ float g_es1[NN * 4], g_ed1[NN * 4];
__device__ float g_es2[NN],     g_ed2[NN];
__device__ int   g_cnt[NN];                  // in-degree (self-cleaning: agg2 re-zeros)
__device__ int   g_slots[(size_t)NN * CAP];  // src lists per dst (slot table)

__device__ __forceinline__ float lrelu(float x) { return x > 0.f ? x : 0.01f * x; }

// packed f32x2 helpers (Blackwell dual-FMA)
__device__ __forceinline__ unsigned long long pack2(float x, float y) {
    unsigned long long r;
    asm("mov.b64 %0, {%1, %2};" : "=l"(r) : "f"(x), "f"(y));
    return r;
}
__device__ __forceinline__ void unpack2(unsigned long long v, float& x, float& y) {
    asm("mov.b64 {%0, %1}, %2;" : "=f"(x), "=f"(y) : "l"(v));
}
__device__ __forceinline__ void ffma2(unsigned long long& acc,
                                      unsigned long long a, unsigned long long b) {
    asm("fma.rn.f32x2 %0, %1, %2, %0;" : "+l"(acc) : "l"(a), "l"(b));
}

// ------------------------- slot-table build -------------------------
__global__ void fill_k(const int* __restrict__ src, const int* __restrict__ dst) {
    int e = blockIdx.x * blockDim.x + threadIdx.x;
    if (e >= NE) return;
    int d = dst[e];
    int pos = atomicAdd(&g_cnt[d], 1);
    if (pos < CAP) g_slots[(size_t)d * CAP + pos] = src[e];
}

// ------------------------- bf16 3-term split GEMM (tensor core) -------------
__device__ __forceinline__ void bfsplit2(float x, float y, uint32_t& hi, uint32_t& lo) {
    asm("cvt.rn.bf16x2.f32 %0, %1, %2;" : "=r"(hi) : "f"(y), "f"(x));
    float hx = __uint_as_float(hi << 16);
    float hy = __uint_as_float(hi & 0xFFFF0000u);
    float lx = x - hx, ly = y - hy;
    asm("cvt.rn.bf16x2.f32 %0, %1, %2;" : "=r"(lo) : "f"(ly), "f"(lx));
}

__device__ __forceinline__ void ldmx2t(uint32_t& r0, uint32_t& r1, uint32_t addr) {
    asm volatile("ldmatrix.sync.aligned.m8n8.x2.trans.shared.b16 {%0,%1}, [%2];"
                 : "=r"(r0), "=r"(r1) : "r"(addr));
}

__device__ __forceinline__ void mma16816(float c[4], const uint32_t a[4],
                                         const uint32_t b[2]) {
    asm volatile(
        "mma.sync.aligned.m16n8k16.row.col.f32.bf16.bf16.f32 "
        "{%0,%1,%2,%3}, {%4,%5,%6,%7}, {%8,%9}, {%0,%1,%2,%3};"
        : "+f"(c[0]), "+f"(c[1]), "+f"(c[2]), "+f"(c[3])
        : "r"(a[0]), "r"(a[1]), "r"(a[2]), "r"(a[3]), "r"(b[0]), "r"(b[1]));
}

template <bool PERM>
__device__ __forceinline__ float4 ldB(const float* __restrict__ B, int N,
                                      int row, int col) {
    if (PERM) {
        int h = col >> 5, o = col & 31;
        return *(const float4*)(B + h * (IND * 32) + row * 32 + o);
    }
    return *(const float4*)(B + (size_t)row * N + col);
}

// C[M,N] = A[M,K] * B[K,N]; C stored fp16. AHALF: A is fp16 (exact in bf16 hi/lo).
// Warp tile WM=BM/WARPS_M, WN=BN/WARPS_N (must be 32).
// EPI==1: fused 4-head es/ed epilogue. EPI==2: single-head es/ed (smem join).
template <int BM, int BN, int BK, int WARPS_M, int WARPS_N, bool PERM, int EPI, bool AHALF>
__global__ __launch_bounds__(WARPS_M * WARPS_N * 32)
void mma_gemm(const void* __restrict__ Av, const float* __restrict__ B,
              __half* __restrict__ Ch, const float* __restrict__ av,
              int M, int N, int K) {
    constexpr int WM = BM / WARPS_M, WN = BN / WARPS_N;
    static_assert(WN == 32, "EPI epilogues require WN==32");
    constexpr int MT = WM / 16, NT = WN / 8;
    constexpr int THREADS = WARPS_M * WARPS_N * 32;
    constexpr int LA = BM * BK / 4 / THREADS;
    constexpr int LB = BK * BN / 4 / THREADS;
    constexpr int AST = BK + 8;
    constexpr int BST = BN + 8;

    __shared__ alignas(16) uint16_t Ah[BM * AST], Al[BM * AST];
    __shared__ alignas(16) uint16_t Bh[BK * BST], Bl[BK * BST];
    __shared__ float s_red[(EPI == 2) ? 2 * BM * 2 : 1];

    const float* A = (const float*)Av;
    const __half* A16 = (const __half*)Av;

    int tid  = threadIdx.x;
    int warp = tid >> 5, lane = tid & 31;
    int g = lane >> 2, tig = lane & 3;
    int wm0 = (warp / WARPS_N) * WM;
    int wn0 = (warp % WARPS_N) * WN;
    int m0  = blockIdx.x * BM;

    uint32_t bh_u32 = (uint32_t)__cvta_generic_to_shared(Bh);
    uint32_t bl_u32 = (uint32_t)__cvta_generic_to_shared(Bl);

    float c[MT][NT][4];
#pragma unroll
    for (int i = 0; i < MT; i++)
#pragma unroll
        for (int j = 0; j < NT; j++)
#pragma unroll
            for (int v = 0; v < 4; v++) c[i][j][v] = 0.f;

    float4 pa[LA];
    uint2  pah[LA];
    float4 pb[LB];
    int ar[LA], ac[LA], br[LB], bc[LB];
#pragma unroll
    for (int it = 0; it < LA; it++) {
        int i = it * THREADS + tid;
        ar[it] = i / (BK / 4);
        ac[it] = (i % (BK / 4)) * 4;
    }
#pragma unroll
    for (int it = 0; it < LB; it++) {
        int i = it * THREADS + tid;
        br[it] = i / (BN / 4);
        bc[it] = (i % (BN / 4)) * 4;
    }

    auto loadA = [&](int it, int k0) {
        int gr = m0 + ar[it]; if (gr >= M) gr = M - 1;
        if (AHALF) pah[it] = *(const uint2*)(A16 + (size_t)gr * K + k0 + ac[it]);
        else       pa[it]  = *(const float4*)(A + (size_t)gr * K + k0 + ac[it]);
    };
    auto storeA = [&](int it) {
        float4 v;
        if (AHALF) {
            float2 f0 = __half22float2(*(const __half2*)&pah[it].x);
            float2 f1 = __half22float2(*(const __half2*)&pah[it].y);
            v = make_float4(f0.x, f0.y, f1.x, f1.y);
        } else v = pa[it];
        uint32_t h0, l0, h1, l1;
        bfsplit2(v.x, v.y, h0, l0);
        bfsplit2(v.z, v.w, h1, l1);
        int base = ar[it] * AST + ac[it];
        *(uint32_t*)&Ah[base] = h0; *(uint32_t*)&Ah[base + 2] = h1;
        *(uint32_t*)&Al[base] = l0; *(uint32_t*)&Al[base + 2] = l1;
    };

#pragma unroll
    for (int it = 0; it < LA; it++) loadA(it, 0);
#pragma unroll
    for (int it = 0; it < LB; it++)
        pb[it] = ldB<PERM>(B, N, br[it], bc[it]);
#pragma unroll
    for (int it = 0; it < LA; it++) storeA(it);
#pragma unroll
    for (int it = 0; it < LB; it++) {
        uint32_t h0, l0, h1, l1;
        bfsplit2(pb[it].x, pb[it].y, h0, l0);
        bfsplit2(pb[it].z, pb[it].w, h1, l1);
        int base = br[it] * BST + bc[it];
        *(uint32_t*)&Bh[base] = h0; *(uint32_t*)&Bh[base + 2] = h1;
        *(uint32_t*)&Bl[base] = l0; *(uint32_t*)&Bl[base + 2] = l1;
    }

    for (int k0 = 0; k0 < K; k0 += BK) {
        __syncthreads();
        bool more = (k0 + BK) < K;
        if (more) {
#pragma unroll
            for (int it = 0; it < LA; it++) loadA(it, k0 + BK);
#pragma unroll
            for (int it = 0; it < LB; it++)
                pb[it] = ldB<PERM>(B, N, k0 + BK + br[it], bc[it]);
        }
#pragma unroll
        for (int ks = 0; ks < BK / 16; ks++) {
            int kb = ks * 16;
            uint32_t af[MT][4], alf[MT][4];
#pragma unroll
            for (int mt = 0; mt < MT; mt++) {
                int mm = wm0 + mt * 16 + g;
                int base = mm * AST + kb + 2 * tig;
                af[mt][0]  = *(const uint32_t*)&Ah[base];
                af[mt][1]  = *(const uint32_t*)&Ah[base + 8 * AST];
                af[mt][2]  = *(const uint32_t*)&Ah[base + 8];
                af[mt][3]  = *(const uint32_t*)&Ah[base + 8 * AST + 8];
                alf[mt][0] = *(const uint32_t*)&Al[base];
                alf[mt][1] = *(const uint32_t*)&Al[base + 8 * AST];
                alf[mt][2] = *(const uint32_t*)&Al[base + 8];
                alf[mt][3] = *(const uint32_t*)&Al[base + 8 * AST + 8];
            }
            uint32_t bf[NT][2], blf[NT][2];
            int krow = kb + (lane & 15);
#pragma unroll
            for (int nt = 0; nt < NT; nt++) {
                uint32_t off = (uint32_t)((krow * BST + wn0 + nt * 8) * 2);
                ldmx2t(bf[nt][0], bf[nt][1], bh_u32 + off);
                ldmx2t(blf[nt][0], blf[nt][1], bl_u32 + off);
            }
#pragma unroll
            for (int mt = 0; mt < MT; mt++)
#pragma unroll
                for (int nt = 0; nt < NT; nt++) {
                    mma16816(c[mt][nt], alf[mt], bf[nt]);
                    mma16816(c[mt][nt], af[mt], blf[nt]);
                    mma16816(c[mt][nt], af[mt], bf[nt]);
                }
        }
        __syncthreads();
        if (more) {
#pragma unroll
            for (int it = 0; it < LA; it++) storeA(it);
#pragma unroll
            for (int it = 0; it < LB; it++) {
                uint32_t h0, l0, h1, l1;
                bfsplit2(pb[it].x, pb[it].y, h0, l0);
                bfsplit2(pb[it].z, pb[it].w, h1, l1);
                int base = br[it] * BST + bc[it];
                *(uint32_t*)&Bh[base] = h0; *(uint32_t*)&Bh[base + 2] = h1;
                *(uint32_t*)&Bl[base] = l0; *(uint32_t*)&Bl[base + 2] = l1;
            }
        }
    }

    // C-store epilogue (fp16)
#pragma unroll
    for (int mt = 0; mt < MT; mt++) {
        int r0 = m0 + wm0 + mt * 16 + g;
        int r1 = r0 + 8;
#pragma unroll
        for (int nt = 0; nt < NT; nt++) {
            int cc = wn0 + nt * 8 + 2 * tig;
            if (r0 < M) *(__half2*)(Ch + (size_t)r0 * N + cc) =
                __floats2half2_rn(c[mt][nt][0], c[mt][nt][1]);
            if (r1 < M) *(__half2*)(Ch + (size_t)r1 * N + cc) =
                __floats2half2_rn(c[mt][nt][2], c[mt][nt][3]);
        }
    }

    if (EPI == 1) {
        int hd = wn0 >> 5;
        const float* as = av + hd * 64;
        const float* ad = as + 32;
#pragma unroll
        for (int mt = 0; mt < MT; mt++) {
            float es0 = 0.f, ed0 = 0.f, es1 = 0.f, ed1 = 0.f;
#pragma unroll
            for (int nt = 0; nt < NT; nt++) {
                int o = nt * 8 + 2 * tig;
                float a0 = as[o], a1v = as[o + 1];
                float d0 = ad[o], d1v = ad[o + 1];
                es0 += c[mt][nt][0] * a0 + c[mt][nt][1] * a1v;
                ed0 += c[mt][nt][0] * d0 + c[mt][nt][1] * d1v;
                es1 += c[mt][nt][2] * a0 + c[mt][nt][3] * a1v;
                ed1 += c[mt][nt][2] * d0 + c[mt][nt][3] * d1v;
            }
            es0 += __shfl_xor_sync(~0u, es0, 1); es0 += __shfl_xor_sync(~0u, es0, 2);
            ed0 += __shfl_xor_sync(~0u, ed0, 1); ed0 += __shfl_xor_sync(~0u, ed0, 2);
            es1 += __shfl_xor_sync(~0u, es1, 1); es1 += __shfl_xor_sync(~0u, es1, 2);
            ed1 += __shfl_xor_sync(~0u, ed1, 1); ed1 += __shfl_xor_sync(~0u, ed1, 2);
            if (tig == 0) {
                int r0 = m0 + wm0 + mt * 16 + g, r1 = r0 + 8;
                if (r0 < M) { g_es1[r0 * 4 + hd] = es0; g_ed1[r0 * 4 + hd] = ed0; }
                if (r1 < M) { g_es1[r1 * 4 + hd] = es1; g_ed1[r1 * 4 + hd] = ed1; }
            }
        }
    }
    if (EPI == 2) {
        int wn = warp % WARPS_N;
#pragma unroll
        for (int mt = 0; mt < MT; mt++) {
            float es0 = 0.f, ed0 = 0.f, es1 = 0.f, ed1 = 0.f;
#pragma unroll
            for (int nt = 0; nt < NT; nt++) {
                int o = wn0 + nt * 8 + 2 * tig;
                float a0 = av[o], a1v = av[o + 1];
                float d0 = av[64 + o], d1v = av[64 + o + 1];
                es0 += c[mt][nt][0] * a0 + c[mt][nt][1] * a1v;
                ed0 += c[mt][nt][0] * d0 + c[mt][nt][1] * d1v;
                es1 += c[mt][nt][2] * a0 + c[mt][nt][3] * a1v;
                ed1 += c[mt][nt][2] * d0 + c[mt][nt][3] * d1v;
            }
            es0 += __shfl_xor_sync(~0u, es0, 1); es0 += __shfl_xor_sync(~0u, es0, 2);
            ed0 += __shfl_xor_sync(~0u, ed0, 1); ed0 += __shfl_xor_sync(~0u, ed0, 2);
            es1 += __shfl_xor_sync(~0u, es1, 1); es1 += __shfl_xor_sync(~0u, es1, 2);
            ed1 += __shfl_xor_sync(~0u, ed1, 1); ed1 += __shfl_xor_sync(~0u, ed1, 2);
            if (tig == 0) {
                int rl0 = wm0 + mt * 16 + g, rl1 = rl0 + 8;
                s_red[(wn * BM + rl0) * 2 + 0] = es0;
                s_red[(wn * BM + rl0) * 2 + 1] = ed0;
                s_red[(wn * BM + rl1) * 2 + 0] = es1;
                s_red[(wn * BM + rl1) * 2 + 1] = ed1;
            }
        }
        __syncthreads();
        if (tid < BM) {
            int r = m0 + tid;
            if (r < M) {
                g_es2[r] = s_red[tid * 2 + 0] + s_red[(BM + tid) * 2 + 0];
                g_ed2[r] = s_red[tid * 2 + 1] + s_red[(BM + tid) * 2 + 1];
            }
        }
    }
}

// ------------------------- fused softmax + aggregate, layer 1 (R10-proven) ----
__global__ __launch_bounds__(256) void agg1_k() {
    __shared__ float2 sm_sw[8][4][33];   // [warp][head][j] = (src bits, w_h)
    int ws   = threadIdx.x >> 5;
    int node = blockIdx.x * 8 + ws;
    int lane = threadIdx.x & 31;
    if (node >= NN) return;
    unsigned long long acc01 = pack2(0.f, 0.f), acc23 = pack2(0.f, 0.f);
    int cnt = g_cnt[node];
    if (cnt > CAP) cnt = CAP;
    int h = lane >> 3;
    if (cnt > 0) {
        const int* slots = g_slots + (size_t)node * CAP;
        float4 ed4 = *(const float4*)(g_ed1 + node * 4);
        if (cnt <= 32) {
            bool act = lane < cnt;
            int s = act ? slots[lane] : 0;
            float4 w = make_float4(0.f, 0.f, 0.f, 0.f);
            if (act) {
                float4 a = *(const float4*)(g_es1 + s * 4);
                w.x = __expf(lrelu(a.x + ed4.x)); w.y = __expf(lrelu(a.y + ed4.y));
                w.z = __expf(lrelu(a.z + ed4.z)); w.w = __expf(lrelu(a.w + ed4.w));
            }
            float4 sum = w;
#pragma unroll
            for (int o = 16; o; o >>= 1) {
                sum.x += __shfl_xor_sync(~0u, sum.x, o);
                sum.y += __shfl_xor_sync(~0u, sum.y, o);
                sum.z += __shfl_xor_sync(~0u, sum.z, o);
                sum.w += __shfl_xor_sync(~0u, sum.w, o);
            }
            float sb = __int_as_float(s);
            sm_sw[ws][0][lane] = make_float2(sb, w.x * (1.f / sum.x));
            sm_sw[ws][1][lane] = make_float2(sb, w.y * (1.f / sum.y));
            sm_sw[ws][2][lane] = make_float2(sb, w.z * (1.f / sum.z));
            sm_sw[ws][3][lane] = make_float2(sb, w.w * (1.f / sum.w));
            __syncwarp();
#pragma unroll 4
            for (int j = 0; j < cnt; j++) {
                float2 sw = sm_sw[ws][h][j];
                int sj = __float_as_int(sw.x);
                unsigned long long w2 = pack2(sw.y, sw.y);
                uint2 zz = *(const uint2*)(g_z1h + ((size_t)sj << 7) + (lane << 2));
                float2 f0 = __half22float2(*(const __half2*)&zz.x);
                float2 f1 = __half22float2(*(const __half2*)&zz.y);
                ffma2(acc01, pack2(f0.x, f0.y), w2);
                ffma2(acc23, pack2(f1.x, f1.y), w2);
            }
        } else {
            float4 sum = make_float4(0.f, 0.f, 0.f, 0.f);
            for (int base = 0; base < cnt; base += 32) {
                if (base + lane < cnt) {
                    int s = slots[base + lane];
                    float4 a = *(const float4*)(g_es1 + s * 4);
                    sum.x += __expf(lrelu(a.x + ed4.x));
                    sum.y += __expf(lrelu(a.y + ed4.y));
                    sum.z += __expf(lrelu(a.z + ed4.z));
                    sum.w += __expf(lrelu(a.w + ed4.w));
                }
            }
#pragma unroll
            for (int o = 16; o; o >>= 1) {
                sum.x += __shfl_xor_sync(~0u, sum.x, o);
                sum.y += __shfl_xor_sync(~0u, sum.y, o);
                sum.z += __shfl_xor_sync(~0u, sum.z, o);
                sum.w += __shfl_xor_sync(~0u, sum.w, o);
            }
            float4 inv = make_float4(1.f / sum.x, 1.f / sum.y, 1.f / sum.z, 1.f / sum.w);
            for (int base = 0; base < cnt; base += 32) {
                int n = min(32, cnt - base);
                if (lane < n) {
                    int s = slots[base + lane];
                    float4 a = *(const float4*)(g_es1 + s * 4);
                    float sb = __int_as_float(s);
                    sm_sw[ws][0][lane] = make_float2(sb, __expf(lrelu(a.x + ed4.x)) * inv.x);
                    sm_sw[ws][1][lane] = make_float2(sb, __expf(lrelu(a.y + ed4.y)) * inv.y);
                    sm_sw[ws][2][lane] = make_float2(sb, __expf(lrelu(a.z + ed4.z)) * inv.z);
                    sm_sw[ws][3][lane] = make_float2(sb, __expf(lrelu(a.w + ed4.w)) * inv.w);
                }
                __syncwarp();
#pragma unroll 4
                for (int j = 0; j < n; j++) {
                    float2 sw = sm_sw[ws][h][j];
                    int sj = __float_as_int(sw.x);
                    unsigned long long w2 = pack2(sw.y, sw.y);
                    uint2 zz = *(const uint2*)(g_z1h + ((size_t)sj << 7) + (lane << 2));
                    float2 f0 = __half22float2(*(const __half2*)&zz.x);
                    float2 f1 = __half22float2(*(const __half2*)&zz.y);
                    ffma2(acc01, pack2(f0.x, f0.y), w2);
                    ffma2(acc23, pack2(f1.x, f1.y), w2);
                }
                __syncwarp();
            }
        }
    }
    float ax, ay, az, aw;
    unpack2(acc01, ax, ay);
    unpack2(acc23, az, aw);
    float4 o;
    o.x = ax > 0.f ? ax : expm1f(ax);
    o.y = ay > 0.f ? ay : expm1f(ay);
    o.z = az > 0.f ? az : expm1f(az);
    o.w = aw > 0.f ? aw : expm1f(aw);
    // store fp16 (GEMM2 A operand; exact in bf16 hi/lo split)
    uint2 st;
    *(__half2*)&st.x = __floats2half2_rn(o.x, o.y);
    *(__half2*)&st.y = __floats2half2_rn(o.z, o.w);
    *(uint2*)(g_h1h + (size_t)node * D1 + lane * 4) = st;
}

// ------------------------- fused softmax + aggregate, layer 2 (R10-proven) ----
__global__ __launch_bounds__(256) void agg2_k(float* __restrict__ out) {
    __shared__ float2 sm_sw[8][33];
    int ws   = threadIdx.x >> 5;
    int node = blockIdx.x * 8 + ws;
    int lane = threadIdx.x & 31;
    if (node >= NN) return;
    unsigned long long acc = pack2(0.f, 0.f);
    int cnt = g_cnt[node];
    if (cnt > CAP) cnt = CAP;
    if (cnt > 0) {
        const int* slots = g_slots + (size_t)node * CAP;
        float edv = g_ed2[node];
        if (cnt <= 32) {
            bool act = lane < cnt;
            int s = act ? slots[lane] : 0;
            float w = act ? __expf(lrelu(g_es2[s] + edv)) : 0.f;
            float sum = w;
#pragma unroll
            for (int o = 16; o; o >>= 1) sum += __shfl_xor_sync(~0u, sum, o);
            sm_sw[ws][lane] = make_float2(__int_as_float(s), w * (1.f / sum));
            __syncwarp();
#pragma unroll 4
            for (int j = 0; j < cnt; j++) {
                float2 sw = sm_sw[ws][j];
                int sj = __float_as_int(sw.x);
                unsigned long long w2 = pack2(sw.y, sw.y);
                __half2 zh = *(const __half2*)(g_z2h + ((size_t)sj << 6) + (lane << 1));
                float2 f = __half22float2(zh);
                ffma2(acc, pack2(f.x, f.y), w2);
            }
        } else {
            float sum = 0.f;
            for (int base = 0; base < cnt; base += 32)
                if (base + lane < cnt)
                    sum += __expf(lrelu(g_es2[slots[base + lane]] + edv));
#pragma unroll
            for (int o = 16; o; o >>= 1) sum += __shfl_xor_sync(~0u, sum, o);
            float inv = 1.f / sum;
            for (int base = 0; base < cnt; base += 32) {
                int n = min(32, cnt - base);
                if (lane < n) {
                    int s = slots[base + lane];
                    sm_sw[ws][lane] = make_float2(__int_as_float(s),
                                                  __expf(lrelu(g_es2[s] + edv)) * inv);
                }
                __syncwarp();
#pragma unroll 4
                for (int j = 0; j < n; j++) {
                    float2 sw = sm_sw[ws][j];
                    int sj = __float_as_int(sw.x);
                    unsigned long long w2 = pack2(sw.y, sw.y);
                    __half2 zh = *(const __half2*)(g_z2h + ((size_t)sj << 6) + (lane << 1));
                    float2 f = __half22float2(zh);
                    ffma2(acc, pack2(f.x, f.y), w2);
                }
                __syncwarp();
            }
        }
    }
    float ax, ay;
    unpack2(acc, ax, ay);
    *(float2*)(out + (size_t)node * D2 + lane * 2) = make_float2(ax, ay);
    // self-cleaning counter: next launch's fill_k needs zeros
    if (lane == 0) g_cnt[node] = 0;
}

// ------------------------- launch -------------------------
extern "C" void kernel_launch(void* const* d_in, const int* in_sizes, int n_in,
                              void* d_out, int out_size) {
    const float* h   = (const float*)d_in[0];
    const int*   src = (const int*)d_in[1];
    const int*   dst = (const int*)d_in[2];
    const float* W1  = (const float*)d_in[3];
    const float* a1  = (const float*)d_in[4];
    const float* W2  = (const float*)d_in[5];
    const float* a2  = (const float*)d_in[6];
    float* out = (float*)d_out;

    void *pz1h, *ph1h, *pz2h;
    cudaGetSymbolAddress(&pz1h, g_z1h);
    cudaGetSymbolAddress(&ph1h, g_h1h);
    cudaGetSymbolAddress(&pz2h, g_z2h);

    int nwb = (NN + 7) / 8;
    int mblocks64 = (NN + 63) / 64;   // BM=64 grids

    // fork: slot-table build on side stream, concurrent with gemm1
    cudaStream_t side;
    cudaStreamCreateWithFlags(&side, cudaStreamNonBlocking);
    cudaEvent_t evRoot, evCsr;
    cudaEventCreateWithFlags(&evRoot, cudaEventDisableTiming);
    cudaEventCreateWithFlags(&evCsr, cudaEventDisableTiming);

    cudaEventRecord(evRoot, 0);
    cudaStreamWaitEvent(side, evRoot, 0);
    fill_k<<<(NE + 255) / 256, 256, 0, side>>>(src, dst);
    cudaEventRecord(evCsr, side);

    // layer 1: BM=64 (2x4 warps, 256 threads) + fused es/ed epilogue
    mma_gemm<64, 128, 32, 2, 4, true, 1, false><<<mblocks64, 256>>>(
        h, W1, (__half*)pz1h, a1, NN, D1, IND);

    cudaStreamWaitEvent(0, evCsr, 0);   // join
    agg1_k<<<nwb, 256>>>();

    // layer 2: BM=64 (2x2 warps, 128 threads), A = fp16 h1
    mma_gemm<64, 64, 32, 2, 2, false, 2, true><<<mblocks64, 128>>>(
        (const void*)ph1h, W2, (__half*)pz2h, a2, NN, D2, D1);
    agg2_k<<<nwb, 256>>>(out);
}

// round 15
// speedup vs baseline: 1.0314x; 1.0008x over previous
#include <cuda_runtime.h>
#include <cuda_fp16.h>
#include <math.h>
#include <stdint.h>

#define NN   50000
#define NE   800000
#define IND  256
#define D1   128   // HEADS*HIDDEN
#define D2   64    // OUT_DIM
#define CAP  128   // max in-degree capacity (Poisson(16) max ~50; 128 is safe)

// ------------------------- device scratch (no allocs) -------------------------
__device__ __half g_z1h[(size_t)NN * D1];    // layer-1 projections (fp16, gather-only)
__device__ __half g_h1h[(size_t)NN * D1];    // elu(layer-1 out), fp16
__device__ __half g_z2h[(size_t)NN * D2];    // layer-2 projections (fp16, gather-only)
__device__ float g_es1[NN * 4], g_ed1[NN * 4];
__device__ float g_es2[NN],     g_ed2[NN];
__device__ int   g_cnt[NN];                  // in-degree (self-cleaning: agg2 re-zeros)
__device__ int   g_slots[(size_t)NN * CAP];  // src lists per dst (slot table)

__device__ __forceinline__ float lrelu(float x) { return x > 0.f ? x : 0.01f * x; }

// packed f32x2 helpers (Blackwell dual-FMA)
__device__ __forceinline__ unsigned long long pack2(float x, float y) {
    unsigned long long r;
    asm("mov.b64 %0, {%1, %2};" : "=l"(r) : "f"(x), "f"(y));
    return r;
}
__device__ __forceinline__ void unpack2(unsigned long long v, float& x, float& y) {
    asm("mov.b64 {%0, %1}, %2;" : "=f"(x), "=f"(y) : "l"(v));
}
__device__ __forceinline__ void ffma2(unsigned long long& acc,
                                      unsigned long long a, unsigned long long b) {
    asm("fma.rn.f32x2 %0, %1, %2, %0;" : "+l"(acc) : "l"(a), "l"(b));
}

// ------------------------- slot-table build -------------------------
__global__ void fill_k(const int* __restrict__ src, const int* __restrict__ dst) {
    int e = blockIdx.x * blockDim.x + threadIdx.x;
    if (e >= NE) return;
    int d = dst[e];
    int pos = atomicAdd(&g_cnt[d], 1);
    if (pos < CAP) g_slots[(size_t)d * CAP + pos] = src[e];
}

// ------------------------- common MMA helpers -------------------------
__device__ __forceinline__ void bfsplit2(float x, float y, uint32_t& hi, uint32_t& lo) {
    asm("cvt.rn.bf16x2.f32 %0, %1, %2;" : "=r"(hi) : "f"(y), "f"(x));
    float hx = __uint_as_float(hi << 16);
    float hy = __uint_as_float(hi & 0xFFFF0000u);
    float lx = x - hx, ly = y - hy;
    asm("cvt.rn.bf16x2.f32 %0, %1, %2;" : "=r"(lo) : "f"(ly), "f"(lx));
}

// fp16 2-term split: hi = fp16(x), lo = fp16(x - hi); 22-bit combined mantissa
__device__ __forceinline__ void h16split2(float x, float y, uint32_t& hi, uint32_t& lo) {
    __half2 h = __floats2half2_rn(x, y);
    float2 hf = __half22float2(h);
    __half2 l = __floats2half2_rn(x - hf.x, y - hf.y);
    hi = *(uint32_t*)&h;
    lo = *(uint32_t*)&l;
}

__device__ __forceinline__ void ldmx2t(uint32_t& r0, uint32_t& r1, uint32_t addr) {
    asm volatile("ldmatrix.sync.aligned.m8n8.x2.trans.shared.b16 {%0,%1}, [%2];"
                 : "=r"(r0), "=r"(r1) : "r"(addr));
}

__device__ __forceinline__ void mma16816(float c[4], const uint32_t a[4],
                                         const uint32_t b[2]) {
    asm volatile(
        "mma.sync.aligned.m16n8k16.row.col.f32.bf16.bf16.f32 "
        "{%0,%1,%2,%3}, {%4,%5,%6,%7}, {%8,%9}, {%0,%1,%2,%3};"
        : "+f"(c[0]), "+f"(c[1]), "+f"(c[2]), "+f"(c[3])
        : "r"(a[0]), "r"(a[1]), "r"(a[2]), "r"(a[3]), "r"(b[0]), "r"(b[1]));
}

__device__ __forceinline__ void mma16816f16(float c[4], const uint32_t a[4],
                                            const uint32_t b[2]) {
    asm volatile(
        "mma.sync.aligned.m16n8k16.row.col.f32.f16.f16.f32 "
        "{%0,%1,%2,%3}, {%4,%5,%6,%7}, {%8,%9}, {%0,%1,%2,%3};"
        : "+f"(c[0]), "+f"(c[1]), "+f"(c[2]), "+f"(c[3])
        : "r"(a[0]), "r"(a[1]), "r"(a[2]), "r"(a[3]), "r"(b[0]), "r"(b[1]));
}

template <bool PERM>
__device__ __forceinline__ float4 ldB(const float* __restrict__ B, int N,
                                      int row, int col) {
    if (PERM) {
        int h = col >> 5, o = col & 31;
        return *(const float4*)(B + h * (IND * 32) + row * 32 + o);
    }
    return *(const float4*)(B + (size_t)row * N + col);
}

// ------------------------- GEMM1: bf16 3-term split, pipelined (R14-proven) --
template <int BM, int BN, int BK, int WARPS_M, int WARPS_N>
__global__ __launch_bounds__(WARPS_M * WARPS_N * 32)
void mma_gemm1(const float* __restrict__ A, const float* __restrict__ B,
               __half* __restrict__ Ch, const float* __restrict__ av,
               int M, int N, int K) {
    constexpr int WM = BM / WARPS_M, WN = BN / WARPS_N;
    static_assert(WN == 32, "epilogue requires WN==32");
    constexpr int MT = WM / 16, NT = WN / 8;
    constexpr int THREADS = WARPS_M * WARPS_N * 32;
    constexpr int LA = BM * BK / 4 / THREADS;
    constexpr int LB = BK * BN / 4 / THREADS;
    constexpr int AST = BK + 8;
    constexpr int BST = BN + 8;

    __shared__ alignas(16) uint16_t Ah[BM * AST], Al[BM * AST];
    __shared__ alignas(16) uint16_t Bh[BK * BST], Bl[BK * BST];

    int tid  = threadIdx.x;
    int warp = tid >> 5, lane = tid & 31;
    int g = lane >> 2, tig = lane & 3;
    int wm0 = (warp / WARPS_N) * WM;
    int wn0 = (warp % WARPS_N) * WN;
    int m0  = blockIdx.x * BM;

    uint32_t bh_u32 = (uint32_t)__cvta_generic_to_shared(Bh);
    uint32_t bl_u32 = (uint32_t)__cvta_generic_to_shared(Bl);

    float c[MT][NT][4];
#pragma unroll
    for (int i = 0; i < MT; i++)
#pragma unroll
        for (int j = 0; j < NT; j++)
#pragma unroll
            for (int v = 0; v < 4; v++) c[i][j][v] = 0.f;

    float4 pa[LA], pb[LB];
    int ar[LA], ac[LA], br[LB], bc[LB];
#pragma unroll
    for (int it = 0; it < LA; it++) {
        int i = it * THREADS + tid;
        ar[it] = i / (BK / 4);
        ac[it] = (i % (BK / 4)) * 4;
    }
#pragma unroll
    for (int it = 0; it < LB; it++) {
        int i = it * THREADS + tid;
        br[it] = i / (BN / 4);
        bc[it] = (i % (BN / 4)) * 4;
    }

#pragma unroll
    for (int it = 0; it < LA; it++) {
        int gr = m0 + ar[it]; if (gr >= M) gr = M - 1;
        pa[it] = *(const float4*)(A + (size_t)gr * K + ac[it]);
    }
#pragma unroll
    for (int it = 0; it < LB; it++)
        pb[it] = ldB<true>(B, N, br[it], bc[it]);
#pragma unroll
    for (int it = 0; it < LA; it++) {
        uint32_t h0, l0, h1, l1;
        bfsplit2(pa[it].x, pa[it].y, h0, l0);
        bfsplit2(pa[it].z, pa[it].w, h1, l1);
        int base = ar[it] * AST + ac[it];
        *(uint32_t*)&Ah[base] = h0; *(uint32_t*)&Ah[base + 2] = h1;
        *(uint32_t*)&Al[base] = l0; *(uint32_t*)&Al[base + 2] = l1;
    }
#pragma unroll
    for (int it = 0; it < LB; it++) {
        uint32_t h0, l0, h1, l1;
        bfsplit2(pb[it].x, pb[it].y, h0, l0);
        bfsplit2(pb[it].z, pb[it].w, h1, l1);
        int base = br[it] * BST + bc[it];
        *(uint32_t*)&Bh[base] = h0; *(uint32_t*)&Bh[base + 2] = h1;
        *(uint32_t*)&Bl[base] = l0; *(uint32_t*)&Bl[base + 2] = l1;
    }

    for (int k0 = 0; k0 < K; k0 += BK) {
        __syncthreads();
        bool more = (k0 + BK) < K;
        if (more) {
#pragma unroll
            for (int it = 0; it < LA; it++) {
                int gr = m0 + ar[it]; if (gr >= M) gr = M - 1;
                pa[it] = *(const float4*)(A + (size_t)gr * K + k0 + BK + ac[it]);
            }
#pragma unroll
            for (int it = 0; it < LB; it++)
                pb[it] = ldB<true>(B, N, k0 + BK + br[it], bc[it]);
        }
#pragma unroll
        for (int ks = 0; ks < BK / 16; ks++) {
            int kb = ks * 16;
            uint32_t af[MT][4], alf[MT][4];
#pragma unroll
            for (int mt = 0; mt < MT; mt++) {
                int mm = wm0 + mt * 16 + g;
                int base = mm * AST + kb + 2 * tig;
                af[mt][0]  = *(const uint32_t*)&Ah[base];
                af[mt][1]  = *(const uint32_t*)&Ah[base + 8 * AST];
                af[mt][2]  = *(const uint32_t*)&Ah[base + 8];
                af[mt][3]  = *(const uint32_t*)&Ah[base + 8 * AST + 8];
                alf[mt][0] = *(const uint32_t*)&Al[base];
                alf[mt][1] = *(const uint32_t*)&Al[base + 8 * AST];
                alf[mt][2] = *(const uint32_t*)&Al[base + 8];
                alf[mt][3] = *(const uint32_t*)&Al[base + 8 * AST + 8];
            }
            uint32_t bf[NT][2], blf[NT][2];
            int krow = kb + (lane & 15);
#pragma unroll
            for (int nt = 0; nt < NT; nt++) {
                uint32_t off = (uint32_t)((krow * BST + wn0 + nt * 8) * 2);
                ldmx2t(bf[nt][0], bf[nt][1], bh_u32 + off);
                ldmx2t(blf[nt][0], blf[nt][1], bl_u32 + off);
            }
#pragma unroll
            for (int mt = 0; mt < MT; mt++)
#pragma unroll
                for (int nt = 0; nt < NT; nt++) {
                    mma16816(c[mt][nt], alf[mt], bf[nt]);
                    mma16816(c[mt][nt], af[mt], blf[nt]);
                    mma16816(c[mt][nt], af[mt], bf[nt]);
                }
        }
        __syncthreads();
        if (more) {
#pragma unroll
            for (int it = 0; it < LA; it++) {
                uint32_t h0, l0, h1, l1;
                bfsplit2(pa[it].x, pa[it].y, h0, l0);
                bfsplit2(pa[it].z, pa[it].w, h1, l1);
                int base = ar[it] * AST + ac[it];
                *(uint32_t*)&Ah[base] = h0; *(uint32_t*)&Ah[base + 2] = h1;
                *(uint32_t*)&Al[base] = l0; *(uint32_t*)&Al[base + 2] = l1;
            }
#pragma unroll
            for (int it = 0; it < LB; it++) {
                uint32_t h0, l0, h1, l1;
                bfsplit2(pb[it].x, pb[it].y, h0, l0);
                bfsplit2(pb[it].z, pb[it].w, h1, l1);
                int base = br[it] * BST + bc[it];
                *(uint32_t*)&Bh[base] = h0; *(uint32_t*)&Bh[base + 2] = h1;
                *(uint32_t*)&Bl[base] = l0; *(uint32_t*)&Bl[base + 2] = l1;
            }
        }
    }

    // C-store (fp16) + fused per-head es/ed epilogue
#pragma unroll
    for (int mt = 0; mt < MT; mt++) {
        int r0 = m0 + wm0 + mt * 16 + g;
        int r1 = r0 + 8;
#pragma unroll
        for (int nt = 0; nt < NT; nt++) {
            int cc = wn0 + nt * 8 + 2 * tig;
            if (r0 < M) *(__half2*)(Ch + (size_t)r0 * N + cc) =
                __floats2half2_rn(c[mt][nt][0], c[mt][nt][1]);
            if (r1 < M) *(__half2*)(Ch + (size_t)r1 * N + cc) =
                __floats2half2_rn(c[mt][nt][2], c[mt][nt][3]);
        }
    }
    {
        int hd = wn0 >> 5;
        const float* as = av + hd * 64;
        const float* ad = as + 32;
#pragma unroll
        for (int mt = 0; mt < MT; mt++) {
            float es0 = 0.f, ed0 = 0.f, es1 = 0.f, ed1 = 0.f;
#pragma unroll
            for (int nt = 0; nt < NT; nt++) {
                int o = nt * 8 + 2 * tig;
                float a0 = as[o], a1v = as[o + 1];
                float d0 = ad[o], d1v = ad[o + 1];
                es0 += c[mt][nt][0] * a0 + c[mt][nt][1] * a1v;
                ed0 += c[mt][nt][0] * d0 + c[mt][nt][1] * d1v;
                es1 += c[mt][nt][2] * a0 + c[mt][nt][3] * a1v;
                ed1 += c[mt][nt][2] * d0 + c[mt][nt][3] * d1v;
            }
            es0 += __shfl_xor_sync(~0u, es0, 1); es0 += __shfl_xor_sync(~0u, es0, 2);
            ed0 += __shfl_xor_sync(~0u, ed0, 1); ed0 += __shfl_xor_sync(~0u, ed0, 2);
            es1 += __shfl_xor_sync(~0u, es1, 1); es1 += __shfl_xor_sync(~0u, es1, 2);
            ed1 += __shfl_xor_sync(~0u, ed1, 1); ed1 += __shfl_xor_sync(~0u, ed1, 2);
            if (tig == 0) {
                int r0 = m0 + wm0 + mt * 16 + g, r1 = r0 + 8;
                if (r0 < M) { g_es1[r0 * 4 + hd] = es0; g_ed1[r0 * 4 + hd] = ed0; }
                if (r1 < M) { g_es1[r1 * 4 + hd] = es1; g_ed1[r1 * 4 + hd] = ed1; }
            }
        }
    }
}

// ------------------------- GEMM2: one-shot full-K, fp16 A, fp16-split B ------
// BM=32, K=D1=128 fully smem-resident; 2 MMAs per tile (A*Bh + A*Bl).
#define G2_BM  32
#define G2_AST 136   // halves: (128+8)
#define G2_BST 72    // halves: (64+8)

__global__ __launch_bounds__(128)
void gemm2_k(const __half* __restrict__ A16, const float* __restrict__ B,
             __half* __restrict__ Ch, const float* __restrict__ av) {
    constexpr int M = NN, N = D2, K = D1;
    __shared__ alignas(16) uint16_t Ah[G2_BM * G2_AST];
    __shared__ alignas(16) uint16_t Bh[K * G2_BST], Bl[K * G2_BST];
    __shared__ float s_red[2 * G2_BM * 2];

    int tid = threadIdx.x, warp = tid >> 5, lane = tid & 31;
    int g = lane >> 2, tig = lane & 3;
    int wm0 = (warp >> 1) * 16;          // warp rows: {0,1}->0, {2,3}->16
    int wn0 = (warp & 1) * 32;
    int m0  = blockIdx.x * G2_BM;

    uint32_t bh_u32 = (uint32_t)__cvta_generic_to_shared(Bh);
    uint32_t bl_u32 = (uint32_t)__cvta_generic_to_shared(Bl);

    // one-shot loads: A (32x128 fp16 = 8 uint2/thread), B (128x64 fp32 = 16 float4/thread)
#pragma unroll
    for (int it = 0; it < 8; it++) {
        int i = it * 128 + tid;
        int row = i >> 5;            // / (K/4 halves per uint2 = 32 groups)
        int col = (i & 31) * 4;
        int gr = m0 + row; if (gr >= M) gr = M - 1;
        uint2 v = *(const uint2*)(A16 + (size_t)gr * K + col);
        *(uint32_t*)&Ah[row * G2_AST + col]     = v.x;
        *(uint32_t*)&Ah[row * G2_AST + col + 2] = v.y;
    }
#pragma unroll
    for (int it = 0; it < 16; it++) {
        int i = it * 128 + tid;
        int row = i >> 4;            // / (N/4 = 16)
        int col = (i & 15) * 4;
        float4 v = *(const float4*)(B + (size_t)row * N + col);
        uint32_t h0, l0, h1, l1;
        h16split2(v.x, v.y, h0, l0);
        h16split2(v.z, v.w, h1, l1);
        int base = row * G2_BST + col;
        *(uint32_t*)&Bh[base] = h0; *(uint32_t*)&Bh[base + 2] = h1;
        *(uint32_t*)&Bl[base] = l0; *(uint32_t*)&Bl[base + 2] = l1;
    }
    __syncthreads();

    float c[4][4];
#pragma unroll
    for (int nt = 0; nt < 4; nt++)
#pragma unroll
        for (int v = 0; v < 4; v++) c[nt][v] = 0.f;

#pragma unroll
    for (int ks = 0; ks < 8; ks++) {
        int kb = ks * 16;
        uint32_t af[4];
        int base = (wm0 + g) * G2_AST + kb + 2 * tig;
        af[0] = *(const uint32_t*)&Ah[base];
        af[1] = *(const uint32_t*)&Ah[base + 8 * G2_AST];
        af[2] = *(const uint32_t*)&Ah[base + 8];
        af[3] = *(const uint32_t*)&Ah[base + 8 * G2_AST + 8];
        int krow = kb + (lane & 15);
#pragma unroll
        for (int nt = 0; nt < 4; nt++) {
            uint32_t bfh[2], bfl[2];
            uint32_t off = (uint32_t)((krow * G2_BST + wn0 + nt * 8) * 2);
            ldmx2t(bfh[0], bfh[1], bh_u32 + off);
            ldmx2t(bfl[0], bfl[1], bl_u32 + off);
            mma16816f16(c[nt], af, bfh);
            mma16816f16(c[nt], af, bfl);
        }
    }

    // C store (fp16)
    int r0 = m0 + wm0 + g, r1 = r0 + 8;
#pragma unroll
    for (int nt = 0; nt < 4; nt++) {
        int cc = wn0 + nt * 8 + 2 * tig;
        if (r0 < M) *(__half2*)(Ch + (size_t)r0 * N + cc) = __floats2half2_rn(c[nt][0], c[nt][1]);
        if (r1 < M) *(__half2*)(Ch + (size_t)r1 * N + cc) = __floats2half2_rn(c[nt][2], c[nt][3]);
    }

    // fused es/ed epilogue (single head; 2 N-warps joined via smem)
    int wn = warp & 1;
    float es0 = 0.f, ed0 = 0.f, es1 = 0.f, ed1 = 0.f;
#pragma unroll
    for (int nt = 0; nt < 4; nt++) {
        int o = wn0 + nt * 8 + 2 * tig;
        float a0 = av[o], a1v = av[o + 1];
        float d0 = av[64 + o], d1v = av[64 + o + 1];
        es0 += c[nt][0] * a0 + c[nt][1] * a1v;
        ed0 += c[nt][0] * d0 + c[nt][1] * d1v;
        es1 += c[nt][2] * a0 + c[nt][3] * a1v;
        ed1 += c[nt][2] * d0 + c[nt][3] * d1v;
    }
    es0 += __shfl_xor_sync(~0u, es0, 1); es0 += __shfl_xor_sync(~0u, es0, 2);
    ed0 += __shfl_xor_sync(~0u, ed0, 1); ed0 += __shfl_xor_sync(~0u, ed0, 2);
    es1 += __shfl_xor_sync(~0u, es1, 1); es1 += __shfl_xor_sync(~0u, es1, 2);
    ed1 += __shfl_xor_sync(~0u, ed1, 1); ed1 += __shfl_xor_sync(~0u, ed1, 2);
    if (tig == 0) {
        int rl0 = wm0 + g, rl1 = rl0 + 8;
        s_red[(wn * G2_BM + rl0) * 2 + 0] = es0;
        s_red[(wn * G2_BM + rl0) * 2 + 1] = ed0;
        s_red[(wn * G2_BM + rl1) * 2 + 0] = es1;
        s_red[(wn * G2_BM + rl1) * 2 + 1] = ed1;
    }
    __syncthreads();
    if (tid < G2_BM) {
        int r = m0 + tid;
        if (r < M) {
            g_es2[r] = s_red[tid * 2 + 0] + s_red[(G2_BM + tid) * 2 + 0];
            g_ed2[r] = s_red[tid * 2 + 1] + s_red[(G2_BM + tid) * 2 + 1];
        }
    }
}

// ------------------------- fused softmax + aggregate, layer 1 (R10-proven) ----
__global__ __launch_bounds__(256) void agg1_k() {
    __shared__ float2 sm_sw[8][4][33];   // [warp][head][j] = (src bits, w_h)
    int ws   = threadIdx.x >> 5;
    int node = blockIdx.x * 8 + ws;
    int lane = threadIdx.x & 31;
    if (node >= NN) return;
    unsigned long long acc01 = pack2(0.f, 0.f), acc23 = pack2(0.f, 0.f);
    int cnt = g_cnt[node];
    if (cnt > CAP) cnt = CAP;
    int h = lane >> 3;
    if (cnt > 0) {
        const int* slots = g_slots + (size_t)node * CAP;
        float4 ed4 = *(const float4*)(g_ed1 + node * 4);
        if (cnt <= 32) {
            bool act = lane < cnt;
            int s = act ? slots[lane] : 0;
            float4 w = make_float4(0.f, 0.f, 0.f, 0.f);
            if (act) {
                float4 a = *(const float4*)(g_es1 + s * 4);
                w.x = __expf(lrelu(a.x + ed4.x)); w.y = __expf(lrelu(a.y + ed4.y));
                w.z = __expf(lrelu(a.z + ed4.z)); w.w = __expf(lrelu(a.w + ed4.w));
            }
            float4 sum = w;
#pragma unroll
            for (int o = 16; o; o >>= 1) {
                sum.x += __shfl_xor_sync(~0u, sum.x, o);
                sum.y += __shfl_xor_sync(~0u, sum.y, o);
                sum.z += __shfl_xor_sync(~0u, sum.z, o);
                sum.w += __shfl_xor_sync(~0u, sum.w, o);
            }
            float sb = __int_as_float(s);
            sm_sw[ws][0][lane] = make_float2(sb, w.x * (1.f / sum.x));
            sm_sw[ws][1][lane] = make_float2(sb, w.y * (1.f / sum.y));
            sm_sw[ws][2][lane] = make_float2(sb, w.z * (1.f / sum.z));
            sm_sw[ws][3][lane] = make_float2(sb, w.w * (1.f / sum.w));
            __syncwarp();
#pragma unroll 4
            for (int j = 0; j < cnt; j++) {
                float2 sw = sm_sw[ws][h][j];
                int sj = __float_as_int(sw.x);
                unsigned long long w2 = pack2(sw.y, sw.y);
                uint2 zz = *(const uint2*)(g_z1h + ((size_t)sj << 7) + (lane << 2));
                float2 f0 = __half22float2(*(const __half2*)&zz.x);
                float2 f1 = __half22float2(*(const __half2*)&zz.y);
                ffma2(acc01, pack2(f0.x, f0.y), w2);
                ffma2(acc23, pack2(f1.x, f1.y), w2);
            }
        } else {
            float4 sum = make_float4(0.f, 0.f, 0.f, 0.f);
            for (int base = 0; base < cnt; base += 32) {
                if (base + lane < cnt) {
                    int s = slots[base + lane];
                    float4 a = *(const float4*)(g_es1 + s * 4);
                    sum.x += __expf(lrelu(a.x + ed4.x));
                    sum.y += __expf(lrelu(a.y + ed4.y));
                    sum.z += __expf(lrelu(a.z + ed4.z));
                    sum.w += __expf(lrelu(a.w + ed4.w));
                }
            }
#pragma unroll
            for (int o = 16; o; o >>= 1) {
                sum.x += __shfl_xor_sync(~0u, sum.x, o);
                sum.y += __shfl_xor_sync(~0u, sum.y, o);
                sum.z += __shfl_xor_sync(~0u, sum.z, o);
                sum.w += __shfl_xor_sync(~0u, sum.w, o);
            }
            float4 inv = make_float4(1.f / sum.x, 1.f / sum.y, 1.f / sum.z, 1.f / sum.w);
            for (int base = 0; base < cnt; base += 32) {
                int n = min(32, cnt - base);
                if (lane < n) {
                    int s = slots[base + lane];
                    float4 a = *(const float4*)(g_es1 + s * 4);
                    float sb = __int_as_float(s);
                    sm_sw[ws][0][lane] = make_float2(sb, __expf(lrelu(a.x + ed4.x)) * inv.x);
                    sm_sw[ws][1][lane] = make_float2(sb, __expf(lrelu(a.y + ed4.y)) * inv.y);
                    sm_sw[ws][2][lane] = make_float2(sb, __expf(lrelu(a.z + ed4.z)) * inv.z);
                    sm_sw[ws][3][lane] = make_float2(sb, __expf(lrelu(a.w + ed4.w)) * inv.w);
                }
                __syncwarp();
#pragma unroll 4
                for (int j = 0; j < n; j++) {
                    float2 sw = sm_sw[ws][h][j];
                    int sj = __float_as_int(sw.x);
                    unsigned long long w2 = pack2(sw.y, sw.y);
                    uint2 zz = *(const uint2*)(g_z1h + ((size_t)sj << 7) + (lane << 2));
                    float2 f0 = __half22float2(*(const __half2*)&zz.x);
                    float2 f1 = __half22float2(*(const __half2*)&zz.y);
                    ffma2(acc01, pack2(f0.x, f0.y), w2);
                    ffma2(acc23, pack2(f1.x, f1.y), w2);
                }
                __syncwarp();
            }
        }
    }
    float ax, ay, az, aw;
    unpack2(acc01, ax, ay);
    unpack2(acc23, az, aw);
    float4 o;
    o.x = ax > 0.f ? ax : expm1f(ax);
    o.y = ay > 0.f ? ay : expm1f(ay);
    o.z = az > 0.f ? az : expm1f(az);
    o.w = aw > 0.f ? aw : expm1f(aw);
    // store fp16 (GEMM2 A operand; exact under fp16 MMA)
    uint2 st;
    *(__half2*)&st.x = __floats2half2_rn(o.x, o.y);
    *(__half2*)&st.y = __floats2half2_rn(o.z, o.w);
    *(uint2*)(g_h1h + (size_t)node * D1 + lane * 4) = st;
}

// ------------------------- fused softmax + aggregate, layer 2 (R10-proven) ----
__global__ __launch_bounds__(256) void agg2_k(float* __restrict__ out) {
    __shared__ float2 sm_sw[8][33];
    int ws   = threadIdx.x >> 5;
    int node = blockIdx.x * 8 + ws;
    int lane = threadIdx.x & 31;
    if (node >= NN) return;
    unsigned long long acc = pack2(0.f, 0.f);
    int cnt = g_cnt[node];
    if (cnt > CAP) cnt = CAP;
    if (cnt > 0) {
        const int* slots = g_slots + (size_t)node * CAP;
        float edv = g_ed2[node];
        if (cnt <= 32) {
            bool act = lane < cnt;
            int s = act ? slots[lane] : 0;
            float w = act ? __expf(lrelu(g_es2[s] + edv)) : 0.f;
            float sum = w;
#pragma unroll
            for (int o = 16; o; o >>= 1) sum += __shfl_xor_sync(~0u, sum, o);
            sm_sw[ws][lane] = make_float2(__int_as_float(s), w * (1.f / sum));
            __syncwarp();
#pragma unroll 4
            for (int j = 0; j < cnt; j++) {
                float2 sw = sm_sw[ws][j];
                int sj = __float_as_int(sw.x);
                unsigned long long w2 = pack2(sw.y, sw.y);
                __half2 zh = *(const __half2*)(g_z2h + ((size_t)sj << 6) + (lane << 1));
                float2 f = __half22float2(zh);
                ffma2(acc, pack2(f.x, f.y), w2);
            }
        } else {
            float sum = 0.f;
            for (int base = 0; base < cnt; base += 32)
                if (base + lane < cnt)
                    sum += __expf(lrelu(g_es2[slots[base + lane]] + edv));
#pragma unroll
            for (int o = 16; o; o >>= 1) sum += __shfl_xor_sync(~0u, sum, o);
            float inv = 1.f / sum;
            for (int base = 0; base < cnt; base += 32) {
                int n = min(32, cnt - base);
                if (lane < n) {
                    int s = slots[base + lane];
                    sm_sw[ws][lane] = make_float2(__int_as_float(s),
                                                  __expf(lrelu(g_es2[s] + edv)) * inv);
                }
                __syncwarp();
#pragma unroll 4
                for (int j = 0; j < n; j++) {
                    float2 sw = sm_sw[ws][j];
                    int sj = __float_as_int(sw.x);
                    unsigned long long w2 = pack2(sw.y, sw.y);
                    __half2 zh = *(const __half2*)(g_z2h + ((size_t)sj << 6) + (lane << 1));
                    float2 f = __half22float2(zh);
                    ffma2(acc, pack2(f.x, f.y), w2);
                }
                __syncwarp();
            }
        }
    }
    float ax, ay;
    unpack2(acc, ax, ay);
    *(float2*)(out + (size_t)node * D2 + lane * 2) = make_float2(ax, ay);
    // self-cleaning counter: next launch's fill_k needs zeros
    if (lane == 0) g_cnt[node] = 0;
}

// ------------------------- launch -------------------------
extern "C" void kernel_launch(void* const* d_in, const int* in_sizes, int n_in,
                              void* d_out, int out_size) {
    const float* h   = (const float*)d_in[0];
    const int*   src = (const int*)d_in[1];
    const int*   dst = (const int*)d_in[2];
    const float* W1  = (const float*)d_in[3];
    const float* a1  = (const float*)d_in[4];
    const float* W2  = (const float*)d_in[5];
    const float* a2  = (const float*)d_in[6];
    float* out = (float*)d_out;

    void *pz1h, *ph1h, *pz2h;
    cudaGetSymbolAddress(&pz1h, g_z1h);
    cudaGetSymbolAddress(&ph1h, g_h1h);
    cudaGetSymbolAddress(&pz2h, g_z2h);

    int nwb = (NN + 7) / 8;
    int mblocks64 = (NN + 63) / 64;
    int g2blocks  = (NN + G2_BM - 1) / G2_BM;

    // fork: slot-table build on side stream, concurrent with gemm1
    cudaStream_t side;
    cudaStreamCreateWithFlags(&side, cudaStreamNonBlocking);
    cudaEvent_t evRoot, evCsr;
    cudaEventCreateWithFlags(&evRoot, cudaEventDisableTiming);
    cudaEventCreateWithFlags(&evCsr, cudaEventDisableTiming);

    cudaEventRecord(evRoot, 0);
    cudaStreamWaitEvent(side, evRoot, 0);
    fill_k<<<(NE + 255) / 256, 256, 0, side>>>(src, dst);
    cudaEventRecord(evCsr, side);

    // layer 1: BM=64 pipelined bf16-split GEMM + fused es/ed epilogue
    mma_gemm1<64, 128, 32, 2, 4><<<mblocks64, 256>>>(
        h, W1, (__half*)pz1h, a1, NN, D1, IND);

    cudaStreamWaitEvent(0, evCsr, 0);   // join
    agg1_k<<<nwb, 256>>>();

    // layer 2: one-shot full-K fp16 GEMM + fused es/ed epilogue
    gemm2_k<<<g2blocks, 128>>>((const __half*)ph1h, W2, (__half*)pz2h, a2);
    agg2_k<<<nwb, 256>>>(out);
}